// round 3
// baseline (speedup 1.0000x reference)
#include <cuda_runtime.h>

// Problem constants (registry shapes): N=100000, E=3200000, F_IN=256, HID=16, C=16, K=2
#define MAXN 100000

// ---------------- device scratch (no allocations allowed) ----------------
__device__ int   g_is64;
__device__ int   g_deg [MAXN];
__device__ float g_dinv[MAXN];
__device__ float g_h1  [MAXN * 32];   // conv1 init-transformed features [N][K*16]
__device__ float g_agg1[MAXN * 32];   // conv1 accumulator (init = root+bias)
__device__ float g_h2  [MAXN * 32];   // conv2 init-transformed features
__device__ float g_agg2[MAXN * 32];   // conv2 accumulator
__device__ float g_W1  [256 * 64];    // packed: cols 0..31 = init (k0,k1), 32..63 = root
__device__ float g_W2  [16 * 64];
__device__ float g_b1  [32];
__device__ float g_b2  [32];

// ---------------- edge-index dtype detection ----------------
// edge_index is declared int64 in the reference, but JAX may canonicalize to
// int32. Values are < 1e5 < 2^31, so if the buffer really is int64 the odd
// int32 words are all zero; if it is int32 they are random node ids.
__global__ void k_detect(const int* __restrict__ ei) {
    if (threadIdx.x == 0 && blockIdx.x == 0) {
        int ok = 1;
        #pragma unroll 1
        for (int i = 0; i < 64; i++)
            if (ei[2 * i + 1] != 0) { ok = 0; break; }
        g_is64 = ok;
    }
}

__global__ void k_zero(int n) {
    int i = blockIdx.x * 256 + threadIdx.x;
    if (i < n) g_deg[i] = 0;
}

// pack weights:  g_W1[f*64 + k*16 + o] = init_w1[k][f][o];  +32 for root
__global__ void k_prep(const float* __restrict__ iw1, const float* __restrict__ rw1,
                       const float* __restrict__ b1,
                       const float* __restrict__ iw2, const float* __restrict__ rw2,
                       const float* __restrict__ b2) {
    int i = blockIdx.x * 256 + threadIdx.x;
    if (i < 16384) {
        int f = i >> 6, c = i & 63;
        if (c < 32) { int k = c >> 4, o = c & 15; g_W1[i] = iw1[k * 4096 + f * 16 + o]; }
        else        { int cc = c - 32; int k = cc >> 4, o = cc & 15; g_W1[i] = rw1[k * 4096 + f * 16 + o]; }
    } else if (i < 16384 + 1024) {
        int j = i - 16384;
        int f = j >> 6, c = j & 63;
        if (c < 32) { int k = c >> 4, o = c & 15; g_W2[j] = iw2[k * 256 + f * 16 + o]; }
        else        { int cc = c - 32; int k = cc >> 4, o = cc & 15; g_W2[j] = rw2[k * 256 + f * 16 + o]; }
    } else if (i < 16384 + 1024 + 32) {
        int j = i - 16384 - 1024; g_b1[j] = b1[j];
    } else if (i < 16384 + 1024 + 64) {
        int j = i - 16384 - 1024 - 32; g_b2[j] = b2[j];
    }
}

__global__ void k_deg(const int* __restrict__ ei, long long E) {
    long long t = blockIdx.x * 256LL + threadIdx.x;
    if (t >= E) return;
    long long pos = E + t;                 // dst index
    int d = g_is64 ? ei[pos << 1] : ei[pos];
    atomicAdd(&g_deg[d], 1);
}

__global__ void k_dinv(int n) {
    int i = blockIdx.x * 256 + threadIdx.x;
    if (i >= n) return;
    int d = g_deg[i];
    g_dinv[i] = (d > 0) ? rsqrtf((float)d) : 0.0f;
}

// ---------------- GEMM1: x[N,256] @ W1[256,64] ----------------
// block = 256 threads, 32 nodes/block. W1 (64KB) + x tile (33KB) in smem.
// thread t: node row = t>>3, output cols c0=(t&7)*8 .. c0+7.
__global__ void __launch_bounds__(256, 2) k_gemm1(const float* __restrict__ x, int nNodes) {
    extern __shared__ float sm[];
    float* sw = sm;             // 16384 floats
    float* sx = sm + 16384;     // 32 rows * 264 (padded)
    int tid = threadIdx.x;
    for (int i = tid; i < 16384; i += 256) sw[i] = g_W1[i];
    int base = blockIdx.x * 32;
    for (int i = tid; i < 8192; i += 256) {
        int r = i >> 8, c = i & 255;
        int n = base + r;
        sx[r * 264 + c] = (n < nNodes) ? x[(long long)n * 256 + c] : 0.0f;
    }
    __syncthreads();

    int r  = tid >> 3;
    int c0 = (tid & 7) * 8;
    int n  = base + r;
    if (n >= nNodes) return;

    float acc[8] = {0.f, 0.f, 0.f, 0.f, 0.f, 0.f, 0.f, 0.f};
    const float* xr = sx + r * 264;
    #pragma unroll 8
    for (int k = 0; k < 256; k++) {
        float xv = xr[k];
        float4 w0 = *reinterpret_cast<const float4*>(sw + k * 64 + c0);
        float4 w1 = *reinterpret_cast<const float4*>(sw + k * 64 + c0 + 4);
        acc[0] += xv * w0.x; acc[1] += xv * w0.y; acc[2] += xv * w0.z; acc[3] += xv * w0.w;
        acc[4] += xv * w1.x; acc[5] += xv * w1.y; acc[6] += xv * w1.z; acc[7] += xv * w1.w;
    }
    if (c0 < 32) {
        float4* o = reinterpret_cast<float4*>(g_h1 + (long long)n * 32 + c0);
        o[0] = make_float4(acc[0], acc[1], acc[2], acc[3]);
        o[1] = make_float4(acc[4], acc[5], acc[6], acc[7]);
    } else {
        int cc = c0 - 32;
        float4* o = reinterpret_cast<float4*>(g_agg1 + (long long)n * 32 + cc);
        o[0] = make_float4(acc[0] + g_b1[cc],     acc[1] + g_b1[cc + 1],
                           acc[2] + g_b1[cc + 2], acc[3] + g_b1[cc + 3]);
        o[1] = make_float4(acc[4] + g_b1[cc + 4], acc[5] + g_b1[cc + 5],
                           acc[6] + g_b1[cc + 6], acc[7] + g_b1[cc + 7]);
    }
}

// ---------------- edge scatter: agg[dst] += h[src] * norm ----------------
// 8 lanes per edge, each lane handles one float4 (rows are 32 floats = 128B).
// which=0: h1->agg1, which=1: h2->agg2.
__global__ void k_scatter(const int* __restrict__ ei, long long E, int which) {
    long long t = blockIdx.x * 256LL + threadIdx.x;
    long long e = t >> 3;
    if (e >= E) return;
    int part = (int)(t & 7);
    int is64 = g_is64;
    int s = is64 ? ei[e << 1] : ei[e];
    long long dp = E + e;
    int d = is64 ? ei[dp << 1] : ei[dp];
    float nrm = g_dinv[s] * g_dinv[d];
    if (nrm == 0.0f) return;
    const float* hsrc = which ? g_h2 : g_h1;
    float*       agg  = which ? g_agg2 : g_agg1;
    float4 v = *reinterpret_cast<const float4*>(hsrc + ((long long)s << 5) + (part << 2));
    float* a = agg + ((long long)d << 5) + (part << 2);
    asm volatile("red.global.add.v4.f32 [%0], {%1, %2, %3, %4};"
                 :: "l"(a), "f"(v.x * nrm), "f"(v.y * nrm), "f"(v.z * nrm), "f"(v.w * nrm)
                 : "memory");
}

// ---------------- conv1 activation + K-mean -> agg_feature (d_out part 2) ----
__global__ void k_act1(float* __restrict__ hfeat, int nNodes) {
    int t = blockIdx.x * 256 + threadIdx.x;
    if (t >= nNodes * 4) return;
    int n = t >> 2, j = t & 3;
    const float4* a = reinterpret_cast<const float4*>(g_agg1) + (long long)n * 8;
    float4 a0 = a[j], a1 = a[4 + j];
    float4 o;
    o.x = 0.5f * (fmaxf(a0.x, 0.f) + fmaxf(a1.x, 0.f));
    o.y = 0.5f * (fmaxf(a0.y, 0.f) + fmaxf(a1.y, 0.f));
    o.z = 0.5f * (fmaxf(a0.z, 0.f) + fmaxf(a1.z, 0.f));
    o.w = 0.5f * (fmaxf(a0.w, 0.f) + fmaxf(a1.w, 0.f));
    reinterpret_cast<float4*>(hfeat)[(long long)n * 4 + j] = o;
}

// ---------------- GEMM2: h[N,16] @ W2[16,64], 4 threads/node ----------------
__global__ void k_gemm2(const float* __restrict__ hfeat, int nNodes) {
    __shared__ float sw[1024];
    for (int i = threadIdx.x; i < 1024; i += 256) sw[i] = g_W2[i];
    __syncthreads();
    int t = blockIdx.x * 256 + threadIdx.x;
    int node = t >> 2;
    if (node >= nNodes) return;
    int q = t & 3;
    const float4* hr = reinterpret_cast<const float4*>(hfeat + (long long)node * 16);
    float h[16];
    #pragma unroll
    for (int j = 0; j < 4; j++) {
        float4 v = hr[j];
        h[4 * j] = v.x; h[4 * j + 1] = v.y; h[4 * j + 2] = v.z; h[4 * j + 3] = v.w;
    }
    float acc[16];
    #pragma unroll
    for (int j = 0; j < 16; j++) acc[j] = 0.f;
    #pragma unroll
    for (int k = 0; k < 16; k++) {
        float xv = h[k];
        const float4* wr = reinterpret_cast<const float4*>(sw + k * 64 + q * 16);
        #pragma unroll
        for (int j = 0; j < 4; j++) {
            float4 w = wr[j];
            acc[4 * j]     += xv * w.x;
            acc[4 * j + 1] += xv * w.y;
            acc[4 * j + 2] += xv * w.z;
            acc[4 * j + 3] += xv * w.w;
        }
    }
    if (q < 2) {
        float4* o = reinterpret_cast<float4*>(g_h2 + (long long)node * 32 + q * 16);
        #pragma unroll
        for (int j = 0; j < 4; j++)
            o[j] = make_float4(acc[4 * j], acc[4 * j + 1], acc[4 * j + 2], acc[4 * j + 3]);
    } else {
        int cc = (q - 2) * 16;
        float4* o = reinterpret_cast<float4*>(g_agg2 + (long long)node * 32 + cc);
        #pragma unroll
        for (int j = 0; j < 4; j++)
            o[j] = make_float4(acc[4 * j]     + g_b2[cc + 4 * j],
                               acc[4 * j + 1] + g_b2[cc + 4 * j + 1],
                               acc[4 * j + 2] + g_b2[cc + 4 * j + 2],
                               acc[4 * j + 3] + g_b2[cc + 4 * j + 3]);
    }
}

// ---------------- K-mean + log_softmax -> d_out part 1 ----------------
__global__ void k_logsm(float* __restrict__ out, int nNodes) {
    int n = blockIdx.x * 256 + threadIdx.x;
    if (n >= nNodes) return;
    const float4* a = reinterpret_cast<const float4*>(g_agg2) + (long long)n * 8;
    float l[16];
    #pragma unroll
    for (int j = 0; j < 4; j++) {
        float4 u = a[j], v = a[4 + j];
        l[4 * j]     = 0.5f * (u.x + v.x);
        l[4 * j + 1] = 0.5f * (u.y + v.y);
        l[4 * j + 2] = 0.5f * (u.z + v.z);
        l[4 * j + 3] = 0.5f * (u.w + v.w);
    }
    float m = l[0];
    #pragma unroll
    for (int i = 1; i < 16; i++) m = fmaxf(m, l[i]);
    float s = 0.f;
    #pragma unroll
    for (int i = 0; i < 16; i++) s += expf(l[i] - m);
    float lg = m + logf(s);
    float4* o = reinterpret_cast<float4*>(out + (long long)n * 16);
    #pragma unroll
    for (int j = 0; j < 4; j++)
        o[j] = make_float4(l[4 * j] - lg, l[4 * j + 1] - lg, l[4 * j + 2] - lg, l[4 * j + 3] - lg);
}

// ---------------- launch ----------------
extern "C" void kernel_launch(void* const* d_in, const int* in_sizes, int n_in,
                              void* d_out, int out_size) {
    const float* x   = (const float*)d_in[0];
    const int*   ei  = (const int*)d_in[1];   // int32 view; dtype auto-detected
    const float* iw1 = (const float*)d_in[2];
    const float* rw1 = (const float*)d_in[3];
    const float* b1  = (const float*)d_in[4];
    const float* iw2 = (const float*)d_in[5];
    const float* rw2 = (const float*)d_in[6];
    const float* b2  = (const float*)d_in[7];
    float* out = (float*)d_out;

    int N = in_sizes[0] / 256;
    long long E = in_sizes[1] / 2;
    float* hfeat = out + (long long)N * 16;   // agg_feature region of d_out

    const int smem1 = (16384 + 32 * 264) * (int)sizeof(float);  // 99328 B
    cudaFuncSetAttribute(k_gemm1, cudaFuncAttributeMaxDynamicSharedMemorySize, smem1);

    int nbN  = (N + 255) / 256;
    int nbN4 = (N * 4 + 255) / 256;
    int nbE  = (int)((E + 255) / 256);
    int nbS  = (int)((E * 8 + 255) / 256);

    k_zero  <<<nbN, 256>>>(N);
    k_detect<<<1, 32>>>(ei);
    k_prep  <<<(16384 + 1024 + 64 + 255) / 256, 256>>>(iw1, rw1, b1, iw2, rw2, b2);
    k_deg   <<<nbE, 256>>>(ei, E);
    k_dinv  <<<nbN, 256>>>(N);
    k_gemm1 <<<(N + 31) / 32, 256, smem1>>>(x, N);
    k_scatter<<<nbS, 256>>>(ei, E, 0);
    k_act1  <<<nbN4, 256>>>(hfeat, N);
    k_gemm2 <<<nbN4, 256>>>(hfeat, N);
    k_scatter<<<nbS, 256>>>(ei, E, 1);
    k_logsm <<<nbN, 256>>>(out, N);
}

// round 5
// speedup vs baseline: 1.1211x; 1.1211x over previous
#include <cuda_runtime.h>

// Problem constants: N=100000, E=3200000, F_IN=256, HID=16, C=16, K=2
#define MAXN 100000
#define MAXE 3200000

// ---------------- device scratch ----------------
__device__ int   g_is64;
__device__ int   g_deg [MAXN];
__device__ float g_dinv[MAXN];
__device__ float g_h1  [MAXN * 32];   // conv1 init-transformed features [N][K*16]
__device__ float g_agg1[MAXN * 32];   // conv1 accumulator (init = root+bias)
__device__ float g_aggr[MAXN * 16];   // conv2 raw aggregation of hfeat
__device__ float g_W1  [256 * 64];    // cols 0..31 = init (k0,k1), 32..63 = root
__device__ float g_W2  [16 * 64];     // same packing
__device__ float g_b1  [32];
__device__ float g_b2  [32];
__device__ int4  g_edges[MAXE];       // {src, dst, norm_bits, pad}

// ---------------- edge-index dtype detection ----------------
__global__ void k_detect(const int* __restrict__ ei) {
    if (threadIdx.x == 0 && blockIdx.x == 0) {
        int ok = 1;
        #pragma unroll 1
        for (int i = 0; i < 64; i++)
            if (ei[2 * i + 1] != 0) { ok = 0; break; }
        g_is64 = ok;
    }
}

__global__ void k_zero(int n) {
    int i = blockIdx.x * 256 + threadIdx.x;
    if (i < n) g_deg[i] = 0;
}

// pack weights:  g_W1[f*64 + k*16 + o] = init_w1[k][f][o];  +32 for root
__global__ void k_prep(const float* __restrict__ iw1, const float* __restrict__ rw1,
                       const float* __restrict__ b1,
                       const float* __restrict__ iw2, const float* __restrict__ rw2,
                       const float* __restrict__ b2) {
    int i = blockIdx.x * 256 + threadIdx.x;
    if (i < 16384) {
        int f = i >> 6, c = i & 63;
        if (c < 32) { int k = c >> 4, o = c & 15; g_W1[i] = iw1[k * 4096 + f * 16 + o]; }
        else        { int cc = c - 32; int k = cc >> 4, o = cc & 15; g_W1[i] = rw1[k * 4096 + f * 16 + o]; }
    } else if (i < 16384 + 1024) {
        int j = i - 16384;
        int f = j >> 6, c = j & 63;
        if (c < 32) { int k = c >> 4, o = c & 15; g_W2[j] = iw2[k * 256 + f * 16 + o]; }
        else        { int cc = c - 32; int k = cc >> 4, o = cc & 15; g_W2[j] = rw2[k * 256 + f * 16 + o]; }
    } else if (i < 16384 + 1024 + 32) {
        int j = i - 16384 - 1024; g_b1[j] = b1[j];
    } else if (i < 16384 + 1024 + 64) {
        int j = i - 16384 - 1024 - 32; g_b2[j] = b2[j];
    }
}

__global__ void k_deg(const int* __restrict__ ei, long long E) {
    long long t = blockIdx.x * 256LL + threadIdx.x;
    if (t >= E) return;
    long long pos = E + t;                 // dst index
    int d = g_is64 ? ei[pos << 1] : ei[pos];
    atomicAdd(&g_deg[d], 1);
}

__global__ void k_dinv(int n) {
    int i = blockIdx.x * 256 + threadIdx.x;
    if (i >= n) return;
    int d = g_deg[i];
    g_dinv[i] = (d > 0) ? rsqrtf((float)d) : 0.0f;
}

// pack edges into 16B records {s, d, nrm, 0}
__global__ void k_eprep(const int* __restrict__ ei, long long E) {
    long long t = blockIdx.x * 256LL + threadIdx.x;
    if (t >= E) return;
    int is64 = g_is64;
    int s = is64 ? ei[t << 1] : ei[t];
    long long dp = E + t;
    int d = is64 ? ei[dp << 1] : ei[dp];
    float nrm = g_dinv[s] * g_dinv[d];
    g_edges[t] = make_int4(s, d, __float_as_int(nrm), 0);
}

// ---------------- GEMM1: x[N,256] @ W1[256,64] ----------------
__global__ void __launch_bounds__(256, 2) k_gemm1(const float* __restrict__ x, int nNodes) {
    extern __shared__ float sm[];
    float* sw = sm;             // 16384 floats
    float* sx = sm + 16384;     // 32 rows * 264 (padded)
    int tid = threadIdx.x;
    for (int i = tid; i < 16384; i += 256) sw[i] = g_W1[i];
    int base = blockIdx.x * 32;
    for (int i = tid; i < 8192; i += 256) {
        int r = i >> 8, c = i & 255;
        int n = base + r;
        sx[r * 264 + c] = (n < nNodes) ? x[(long long)n * 256 + c] : 0.0f;
    }
    __syncthreads();

    int r  = tid >> 3;
    int c0 = (tid & 7) * 8;
    int n  = base + r;
    if (n >= nNodes) return;

    float acc[8] = {0.f, 0.f, 0.f, 0.f, 0.f, 0.f, 0.f, 0.f};
    const float* xr = sx + r * 264;
    #pragma unroll 8
    for (int k = 0; k < 256; k++) {
        float xv = xr[k];
        float4 w0 = *reinterpret_cast<const float4*>(sw + k * 64 + c0);
        float4 w1 = *reinterpret_cast<const float4*>(sw + k * 64 + c0 + 4);
        acc[0] += xv * w0.x; acc[1] += xv * w0.y; acc[2] += xv * w0.z; acc[3] += xv * w0.w;
        acc[4] += xv * w1.x; acc[5] += xv * w1.y; acc[6] += xv * w1.z; acc[7] += xv * w1.w;
    }
    if (c0 < 32) {
        float4* o = reinterpret_cast<float4*>(g_h1 + (long long)n * 32 + c0);
        o[0] = make_float4(acc[0], acc[1], acc[2], acc[3]);
        o[1] = make_float4(acc[4], acc[5], acc[6], acc[7]);
    } else {
        int cc = c0 - 32;
        float4* o = reinterpret_cast<float4*>(g_agg1 + (long long)n * 32 + cc);
        o[0] = make_float4(acc[0] + g_b1[cc],     acc[1] + g_b1[cc + 1],
                           acc[2] + g_b1[cc + 2], acc[3] + g_b1[cc + 3]);
        o[1] = make_float4(acc[4] + g_b1[cc + 4], acc[5] + g_b1[cc + 5],
                           acc[6] + g_b1[cc + 6], acc[7] + g_b1[cc + 7]);
    }
}

// ---------------- scatter1: agg1[dst] += h1[src]*norm (32 floats, 8 lanes/edge) ----
__global__ void k_scatter1(long long E) {
    long long t = blockIdx.x * 256LL + threadIdx.x;
    long long e = t >> 3;
    if (e >= E) return;
    int part = (int)(t & 7);
    int4 rec = g_edges[e];
    float nrm = __int_as_float(rec.z);
    float4 v = *reinterpret_cast<const float4*>(g_h1 + ((long long)rec.x << 5) + (part << 2));
    float* a = g_agg1 + ((long long)rec.y << 5) + (part << 2);
    asm volatile("red.global.add.v4.f32 [%0], {%1, %2, %3, %4};"
                 :: "l"(a), "f"(v.x * nrm), "f"(v.y * nrm), "f"(v.z * nrm), "f"(v.w * nrm)
                 : "memory");
}

// ---------------- conv1 relu + K-mean -> hfeat; zero g_aggr ----------------
__global__ void k_act1(float* __restrict__ hfeat, int nNodes) {
    int t = blockIdx.x * 256 + threadIdx.x;
    if (t >= nNodes * 4) return;
    int n = t >> 2, j = t & 3;
    const float4* a = reinterpret_cast<const float4*>(g_agg1) + (long long)n * 8;
    float4 a0 = a[j], a1 = a[4 + j];
    float4 o;
    o.x = 0.5f * (fmaxf(a0.x, 0.f) + fmaxf(a1.x, 0.f));
    o.y = 0.5f * (fmaxf(a0.y, 0.f) + fmaxf(a1.y, 0.f));
    o.z = 0.5f * (fmaxf(a0.z, 0.f) + fmaxf(a1.z, 0.f));
    o.w = 0.5f * (fmaxf(a0.w, 0.f) + fmaxf(a1.w, 0.f));
    reinterpret_cast<float4*>(hfeat)[(long long)n * 4 + j] = o;
    reinterpret_cast<float4*>(g_aggr)[(long long)n * 4 + j] = make_float4(0.f, 0.f, 0.f, 0.f);
}

// ---------------- scatter2: aggr[dst] += hfeat[src]*norm (16 floats, 4 lanes/edge) ----
__global__ void k_scatter2(const float* __restrict__ hfeat, long long E) {
    long long t = blockIdx.x * 256LL + threadIdx.x;
    long long e = t >> 2;
    if (e >= E) return;
    int part = (int)(t & 3);
    int4 rec = g_edges[e];
    float nrm = __int_as_float(rec.z);
    float4 v = *reinterpret_cast<const float4*>(hfeat + ((long long)rec.x << 4) + (part << 2));
    float* a = g_aggr + ((long long)rec.y << 4) + (part << 2);
    asm volatile("red.global.add.v4.f32 [%0], {%1, %2, %3, %4};"
                 :: "l"(a), "f"(v.x * nrm), "f"(v.y * nrm), "f"(v.z * nrm), "f"(v.w * nrm)
                 : "memory");
}

// ---------------- final: GEMM2 on aggregated + root + bias, K-mean, log_softmax ----
__global__ void __launch_bounds__(256) k_final(const float* __restrict__ hfeat,
                                               float* __restrict__ out, int nNodes) {
    __shared__ float sw[1024];
    __shared__ float sb[32];
    for (int i = threadIdx.x; i < 1024; i += 256) sw[i] = g_W2[i];
    if (threadIdx.x < 32) sb[threadIdx.x] = g_b2[threadIdx.x];
    __syncthreads();
    int n = blockIdx.x * 256 + threadIdx.x;
    if (n >= nNodes) return;

    float hr[16], ag[16];
    const float4* hp = reinterpret_cast<const float4*>(hfeat + (long long)n * 16);
    const float4* ap = reinterpret_cast<const float4*>(g_aggr) + (long long)n * 4;
    #pragma unroll
    for (int j = 0; j < 4; j++) {
        float4 h4 = hp[j], a4 = ap[j];
        hr[4 * j] = h4.x; hr[4 * j + 1] = h4.y; hr[4 * j + 2] = h4.z; hr[4 * j + 3] = h4.w;
        ag[4 * j] = a4.x; ag[4 * j + 1] = a4.y; ag[4 * j + 2] = a4.z; ag[4 * j + 3] = a4.w;
    }

    float l[16];
    #pragma unroll
    for (int o = 0; o < 16; o++) l[o] = 0.f;
    #pragma unroll
    for (int k = 0; k < 2; k++) {
        float acc[16];
        #pragma unroll
        for (int o = 0; o < 16; o++) acc[o] = sb[k * 16 + o];
        #pragma unroll
        for (int f = 0; f < 16; f++) {
            float av = ag[f], hv = hr[f];
            const float* wi = sw + f * 64 + k * 16;       // init
            const float* wr = wi + 32;                    // root
            #pragma unroll
            for (int o = 0; o < 16; o++)
                acc[o] += av * wi[o] + hv * wr[o];
        }
        #pragma unroll
        for (int o = 0; o < 16; o++) l[o] += 0.5f * acc[o];
    }

    float m = l[0];
    #pragma unroll
    for (int i = 1; i < 16; i++) m = fmaxf(m, l[i]);
    float s = 0.f;
    #pragma unroll
    for (int i = 0; i < 16; i++) s += expf(l[i] - m);
    float lg = m + logf(s);
    float4* o4 = reinterpret_cast<float4*>(out + (long long)n * 16);
    #pragma unroll
    for (int j = 0; j < 4; j++)
        o4[j] = make_float4(l[4 * j] - lg, l[4 * j + 1] - lg,
                            l[4 * j + 2] - lg, l[4 * j + 3] - lg);
}

// ---------------- launch ----------------
extern "C" void kernel_launch(void* const* d_in, const int* in_sizes, int n_in,
                              void* d_out, int out_size) {
    const float* x   = (const float*)d_in[0];
    const int*   ei  = (const int*)d_in[1];
    const float* iw1 = (const float*)d_in[2];
    const float* rw1 = (const float*)d_in[3];
    const float* b1  = (const float*)d_in[4];
    const float* iw2 = (const float*)d_in[5];
    const float* rw2 = (const float*)d_in[6];
    const float* b2  = (const float*)d_in[7];
    float* out = (float*)d_out;

    int N = in_sizes[0] / 256;
    long long E = in_sizes[1] / 2;
    float* hfeat = out + (long long)N * 16;   // agg_feature region of d_out

    const int smem1 = (16384 + 32 * 264) * (int)sizeof(float);  // 99328 B
    cudaFuncSetAttribute(k_gemm1, cudaFuncAttributeMaxDynamicSharedMemorySize, smem1);

    int nbN  = (N + 255) / 256;
    int nbN4 = (N * 4 + 255) / 256;
    int nbE  = (int)((E + 255) / 256);
    int nbS1 = (int)((E * 8 + 255) / 256);
    int nbS2 = (int)((E * 4 + 255) / 256);

    k_zero   <<<nbN, 256>>>(N);
    k_detect <<<1, 32>>>(ei);
    k_prep   <<<(16384 + 1024 + 64 + 255) / 256, 256>>>(iw1, rw1, b1, iw2, rw2, b2);
    k_deg    <<<nbE, 256>>>(ei, E);
    k_dinv   <<<nbN, 256>>>(N);
    k_eprep  <<<nbE, 256>>>(ei, E);
    k_gemm1  <<<(N + 31) / 32, 256, smem1>>>(x, N);
    k_scatter1<<<nbS1, 256>>>(E);
    k_act1   <<<nbN4, 256>>>(hfeat, N);
    k_scatter2<<<nbS2, 256>>>(hfeat, E);
    k_final  <<<nbN, 256>>>(hfeat, out, N);
}

// round 6
// speedup vs baseline: 1.2320x; 1.0990x over previous
#include <cuda_runtime.h>

// Problem constants: N=100000, E=3200000, F_IN=256, HID=16, C=16, K=2
#define MAXN 131072
#define MAXE 3200000

// ---------------- device scratch ----------------
__device__ int   g_is64;
__device__ int   g_deg [MAXN];
__device__ int   g_off [MAXN];
__device__ int   g_cur [MAXN];
__device__ int   g_bsum[512];
__device__ int   g_boff[512];
__device__ float g_dinv[MAXN];
__device__ float g_h1  [MAXN * 32];   // conv1 init-transformed features [N][K*16]
__device__ float g_agg1[MAXN * 32];   // conv1 root+bias (init value of accumulator)
__device__ float g_aggr[MAXN * 16];   // conv2 raw aggregation of hfeat
__device__ float g_W1  [256 * 64];    // cols 0..31 = init (k0,k1), 32..63 = root
__device__ float g_W2  [16 * 64];
__device__ float g_b1  [32];
__device__ float g_b2  [32];
__device__ int2  g_csr [MAXE];        // dst-sorted: {src, norm_bits}

// ---------------- edge-index dtype detection ----------------
__global__ void k_detect(const int* __restrict__ ei) {
    if (threadIdx.x == 0 && blockIdx.x == 0) {
        int ok = 1;
        #pragma unroll 1
        for (int i = 0; i < 64; i++)
            if (ei[2 * i + 1] != 0) { ok = 0; break; }
        g_is64 = ok;
    }
}

__global__ void k_zero(int n) {
    int i = blockIdx.x * 256 + threadIdx.x;
    if (i < n) g_deg[i] = 0;
}

// pack weights:  g_W1[f*64 + k*16 + o] = init_w1[k][f][o];  +32 for root
__global__ void k_prep(const float* __restrict__ iw1, const float* __restrict__ rw1,
                       const float* __restrict__ b1,
                       const float* __restrict__ iw2, const float* __restrict__ rw2,
                       const float* __restrict__ b2) {
    int i = blockIdx.x * 256 + threadIdx.x;
    if (i < 16384) {
        int f = i >> 6, c = i & 63;
        if (c < 32) { int k = c >> 4, o = c & 15; g_W1[i] = iw1[k * 4096 + f * 16 + o]; }
        else        { int cc = c - 32; int k = cc >> 4, o = cc & 15; g_W1[i] = rw1[k * 4096 + f * 16 + o]; }
    } else if (i < 16384 + 1024) {
        int j = i - 16384;
        int f = j >> 6, c = j & 63;
        if (c < 32) { int k = c >> 4, o = c & 15; g_W2[j] = iw2[k * 256 + f * 16 + o]; }
        else        { int cc = c - 32; int k = cc >> 4, o = cc & 15; g_W2[j] = rw2[k * 256 + f * 16 + o]; }
    } else if (i < 16384 + 1024 + 32) {
        int j = i - 16384 - 1024; g_b1[j] = b1[j];
    } else if (i < 16384 + 1024 + 64) {
        int j = i - 16384 - 1024 - 32; g_b2[j] = b2[j];
    }
}

__global__ void k_deg(const int* __restrict__ ei, long long E) {
    long long t = blockIdx.x * 256LL + threadIdx.x;
    if (t >= E) return;
    long long pos = E + t;                 // dst index
    int d = g_is64 ? ei[pos << 1] : ei[pos];
    atomicAdd(&g_deg[d], 1);
}

__global__ void k_dinv(int n) {
    int i = blockIdx.x * 256 + threadIdx.x;
    if (i >= n) return;
    int d = g_deg[i];
    g_dinv[i] = (d > 0) ? rsqrtf((float)d) : 0.0f;
}

// ---------------- 3-phase exclusive scan of g_deg -> g_off (and g_cur) ----
// phase A: per-block (1024 elems) totals
__global__ void k_scanA(int n) {
    __shared__ int sm[256];
    int base = blockIdx.x * 1024;
    int t = threadIdx.x;
    int s = 0;
    #pragma unroll
    for (int j = 0; j < 4; j++) {
        int i = base + t * 4 + j;
        if (i < n) s += g_deg[i];
    }
    sm[t] = s; __syncthreads();
    #pragma unroll
    for (int o = 128; o > 0; o >>= 1) {
        if (t < o) sm[t] += sm[t + o];
        __syncthreads();
    }
    if (t == 0) g_bsum[blockIdx.x] = sm[0];
}
// phase B: scan of block totals (single block, up to 512 blocks)
__global__ void k_scanB(int nb) {
    __shared__ int sm[512];
    int t = threadIdx.x;                   // 512 threads
    int v0 = (t < nb) ? g_bsum[t] : 0;
    sm[t] = v0; __syncthreads();
    #pragma unroll
    for (int o = 1; o < 512; o <<= 1) {
        int v = (t >= o) ? sm[t - o] : 0;
        __syncthreads();
        sm[t] += v;
        __syncthreads();
    }
    if (t < nb) g_boff[t] = sm[t] - v0;    // exclusive
}
// phase C: per-element exclusive offsets
__global__ void k_scanC(int n) {
    __shared__ int sm[256];
    int base = blockIdx.x * 1024;
    int t = threadIdx.x;
    int d[4]; int s = 0;
    #pragma unroll
    for (int j = 0; j < 4; j++) {
        int i = base + t * 4 + j;
        d[j] = (i < n) ? g_deg[i] : 0;
        s += d[j];
    }
    sm[t] = s; __syncthreads();
    #pragma unroll
    for (int o = 1; o < 256; o <<= 1) {
        int v = (t >= o) ? sm[t - o] : 0;
        __syncthreads();
        sm[t] += v;
        __syncthreads();
    }
    int excl = sm[t] - s + g_boff[blockIdx.x];
    #pragma unroll
    for (int j = 0; j < 4; j++) {
        int i = base + t * 4 + j;
        if (i < n) { g_off[i] = excl; g_cur[i] = excl; excl += d[j]; }
    }
}

// ---------------- fill CSR: dst-sorted {src, norm} records ----------------
__global__ void k_fill(const int* __restrict__ ei, long long E) {
    long long t = blockIdx.x * 256LL + threadIdx.x;
    if (t >= E) return;
    int is64 = g_is64;
    int s = is64 ? ei[t << 1] : ei[t];
    long long dp = E + t;
    int d = is64 ? ei[dp << 1] : ei[dp];
    float nrm = g_dinv[s] * g_dinv[d];
    int pos = atomicAdd(&g_cur[d], 1);
    g_csr[pos] = make_int2(s, __float_as_int(nrm));
}

// ---------------- GEMM1: x[N,256] @ W1[256,64] ----------------
__global__ void __launch_bounds__(256, 2) k_gemm1(const float* __restrict__ x, int nNodes) {
    extern __shared__ float sm[];
    float* sw = sm;             // 16384 floats
    float* sx = sm + 16384;     // 32 rows * 264 (padded)
    int tid = threadIdx.x;
    for (int i = tid; i < 16384; i += 256) sw[i] = g_W1[i];
    int base = blockIdx.x * 32;
    for (int i = tid; i < 8192; i += 256) {
        int r = i >> 8, c = i & 255;
        int n = base + r;
        sx[r * 264 + c] = (n < nNodes) ? x[(long long)n * 256 + c] : 0.0f;
    }
    __syncthreads();

    int r  = tid >> 3;
    int c0 = (tid & 7) * 8;
    int n  = base + r;
    if (n >= nNodes) return;

    float acc[8] = {0.f, 0.f, 0.f, 0.f, 0.f, 0.f, 0.f, 0.f};
    const float* xr = sx + r * 264;
    #pragma unroll 8
    for (int k = 0; k < 256; k++) {
        float xv = xr[k];
        float4 w0 = *reinterpret_cast<const float4*>(sw + k * 64 + c0);
        float4 w1 = *reinterpret_cast<const float4*>(sw + k * 64 + c0 + 4);
        acc[0] += xv * w0.x; acc[1] += xv * w0.y; acc[2] += xv * w0.z; acc[3] += xv * w0.w;
        acc[4] += xv * w1.x; acc[5] += xv * w1.y; acc[6] += xv * w1.z; acc[7] += xv * w1.w;
    }
    if (c0 < 32) {
        float4* o = reinterpret_cast<float4*>(g_h1 + (long long)n * 32 + c0);
        o[0] = make_float4(acc[0], acc[1], acc[2], acc[3]);
        o[1] = make_float4(acc[4], acc[5], acc[6], acc[7]);
    } else {
        int cc = c0 - 32;
        float4* o = reinterpret_cast<float4*>(g_agg1 + (long long)n * 32 + cc);
        o[0] = make_float4(acc[0] + g_b1[cc],     acc[1] + g_b1[cc + 1],
                           acc[2] + g_b1[cc + 2], acc[3] + g_b1[cc + 3]);
        o[1] = make_float4(acc[4] + g_b1[cc + 4], acc[5] + g_b1[cc + 5],
                           acc[6] + g_b1[cc + 6], acc[7] + g_b1[cc + 7]);
    }
}

// ---------------- gather1: per node, accumulate in-edges of h1; relu+mean ----
// 8 lanes/node (4 cols each). Lanes p and p+4 hold k=0 / k=1 stacks; combined
// via shfl_xor(4). No atomics.
__global__ void __launch_bounds__(256) k_gather1(float* __restrict__ hfeat, int nNodes) {
    int t = blockIdx.x * 256 + threadIdx.x;
    int node = t >> 3;
    bool valid = node < nNodes;
    int n = valid ? node : (nNodes - 1);
    int part = t & 7;
    int beg = g_off[n];
    int end = beg + g_deg[n];
    float4 acc = *reinterpret_cast<const float4*>(g_agg1 + ((long long)n << 5) + (part << 2));
    int i = beg;
    for (; i + 4 <= end; i += 4) {
        int2 r0 = g_csr[i], r1 = g_csr[i + 1], r2 = g_csr[i + 2], r3 = g_csr[i + 3];
        float4 v0 = *reinterpret_cast<const float4*>(g_h1 + ((long long)r0.x << 5) + (part << 2));
        float4 v1 = *reinterpret_cast<const float4*>(g_h1 + ((long long)r1.x << 5) + (part << 2));
        float4 v2 = *reinterpret_cast<const float4*>(g_h1 + ((long long)r2.x << 5) + (part << 2));
        float4 v3 = *reinterpret_cast<const float4*>(g_h1 + ((long long)r3.x << 5) + (part << 2));
        float n0 = __int_as_float(r0.y), n1 = __int_as_float(r1.y);
        float n2 = __int_as_float(r2.y), n3 = __int_as_float(r3.y);
        acc.x += v0.x * n0 + v1.x * n1 + v2.x * n2 + v3.x * n3;
        acc.y += v0.y * n0 + v1.y * n1 + v2.y * n2 + v3.y * n3;
        acc.z += v0.z * n0 + v1.z * n1 + v2.z * n2 + v3.z * n3;
        acc.w += v0.w * n0 + v1.w * n1 + v2.w * n2 + v3.w * n3;
    }
    for (; i < end; i++) {
        int2 r = g_csr[i];
        float nrm = __int_as_float(r.y);
        float4 v = *reinterpret_cast<const float4*>(g_h1 + ((long long)r.x << 5) + (part << 2));
        acc.x += v.x * nrm; acc.y += v.y * nrm; acc.z += v.z * nrm; acc.w += v.w * nrm;
    }
    acc.x = fmaxf(acc.x, 0.f); acc.y = fmaxf(acc.y, 0.f);
    acc.z = fmaxf(acc.z, 0.f); acc.w = fmaxf(acc.w, 0.f);
    float ox = 0.5f * (acc.x + __shfl_xor_sync(0xffffffffu, acc.x, 4));
    float oy = 0.5f * (acc.y + __shfl_xor_sync(0xffffffffu, acc.y, 4));
    float oz = 0.5f * (acc.z + __shfl_xor_sync(0xffffffffu, acc.z, 4));
    float ow = 0.5f * (acc.w + __shfl_xor_sync(0xffffffffu, acc.w, 4));
    if (valid && part < 4)
        reinterpret_cast<float4*>(hfeat)[((long long)n << 2) + part] =
            make_float4(ox, oy, oz, ow);
}

// ---------------- gather2: aggr[n] = sum over in-edges of hfeat[src]*norm ----
__global__ void __launch_bounds__(256) k_gather2(const float* __restrict__ hfeat, int nNodes) {
    int t = blockIdx.x * 256 + threadIdx.x;
    int n = t >> 2;
    if (n >= nNodes) return;
    int part = t & 3;
    int beg = g_off[n];
    int end = beg + g_deg[n];
    float4 acc = make_float4(0.f, 0.f, 0.f, 0.f);
    int i = beg;
    for (; i + 4 <= end; i += 4) {
        int2 r0 = g_csr[i], r1 = g_csr[i + 1], r2 = g_csr[i + 2], r3 = g_csr[i + 3];
        float4 v0 = *reinterpret_cast<const float4*>(hfeat + ((long long)r0.x << 4) + (part << 2));
        float4 v1 = *reinterpret_cast<const float4*>(hfeat + ((long long)r1.x << 4) + (part << 2));
        float4 v2 = *reinterpret_cast<const float4*>(hfeat + ((long long)r2.x << 4) + (part << 2));
        float4 v3 = *reinterpret_cast<const float4*>(hfeat + ((long long)r3.x << 4) + (part << 2));
        float n0 = __int_as_float(r0.y), n1 = __int_as_float(r1.y);
        float n2 = __int_as_float(r2.y), n3 = __int_as_float(r3.y);
        acc.x += v0.x * n0 + v1.x * n1 + v2.x * n2 + v3.x * n3;
        acc.y += v0.y * n0 + v1.y * n1 + v2.y * n2 + v3.y * n3;
        acc.z += v0.z * n0 + v1.z * n1 + v2.z * n2 + v3.z * n3;
        acc.w += v0.w * n0 + v1.w * n1 + v2.w * n2 + v3.w * n3;
    }
    for (; i < end; i++) {
        int2 r = g_csr[i];
        float nrm = __int_as_float(r.y);
        float4 v = *reinterpret_cast<const float4*>(hfeat + ((long long)r.x << 4) + (part << 2));
        acc.x += v.x * nrm; acc.y += v.y * nrm; acc.z += v.z * nrm; acc.w += v.w * nrm;
    }
    reinterpret_cast<float4*>(g_aggr)[((long long)n << 2) + part] = acc;
}

// ---------------- final: GEMM2 on aggregated + root + bias, K-mean, log_softmax ----
__global__ void __launch_bounds__(256) k_final(const float* __restrict__ hfeat,
                                               float* __restrict__ out, int nNodes) {
    __shared__ float sw[1024];
    __shared__ float sb[32];
    for (int i = threadIdx.x; i < 1024; i += 256) sw[i] = g_W2[i];
    if (threadIdx.x < 32) sb[threadIdx.x] = g_b2[threadIdx.x];
    __syncthreads();
    int n = blockIdx.x * 256 + threadIdx.x;
    if (n >= nNodes) return;

    float hr[16], ag[16];
    const float4* hp = reinterpret_cast<const float4*>(hfeat + (long long)n * 16);
    const float4* ap = reinterpret_cast<const float4*>(g_aggr) + (long long)n * 4;
    #pragma unroll
    for (int j = 0; j < 4; j++) {
        float4 h4 = hp[j], a4 = ap[j];
        hr[4 * j] = h4.x; hr[4 * j + 1] = h4.y; hr[4 * j + 2] = h4.z; hr[4 * j + 3] = h4.w;
        ag[4 * j] = a4.x; ag[4 * j + 1] = a4.y; ag[4 * j + 2] = a4.z; ag[4 * j + 3] = a4.w;
    }

    float l[16];
    #pragma unroll
    for (int o = 0; o < 16; o++) l[o] = 0.f;
    #pragma unroll
    for (int k = 0; k < 2; k++) {
        float acc[16];
        #pragma unroll
        for (int o = 0; o < 16; o++) acc[o] = sb[k * 16 + o];
        #pragma unroll
        for (int f = 0; f < 16; f++) {
            float av = ag[f], hv = hr[f];
            const float* wi = sw + f * 64 + k * 16;       // init
            const float* wr = wi + 32;                    // root
            #pragma unroll
            for (int o = 0; o < 16; o++)
                acc[o] += av * wi[o] + hv * wr[o];
        }
        #pragma unroll
        for (int o = 0; o < 16; o++) l[o] += 0.5f * acc[o];
    }

    float m = l[0];
    #pragma unroll
    for (int i = 1; i < 16; i++) m = fmaxf(m, l[i]);
    float s = 0.f;
    #pragma unroll
    for (int i = 0; i < 16; i++) s += expf(l[i] - m);
    float lg = m + logf(s);
    float4* o4 = reinterpret_cast<float4*>(out + (long long)n * 16);
    #pragma unroll
    for (int j = 0; j < 4; j++)
        o4[j] = make_float4(l[4 * j] - lg, l[4 * j + 1] - lg,
                            l[4 * j + 2] - lg, l[4 * j + 3] - lg);
}

// ---------------- launch ----------------
extern "C" void kernel_launch(void* const* d_in, const int* in_sizes, int n_in,
                              void* d_out, int out_size) {
    const float* x   = (const float*)d_in[0];
    const int*   ei  = (const int*)d_in[1];
    const float* iw1 = (const float*)d_in[2];
    const float* rw1 = (const float*)d_in[3];
    const float* b1  = (const float*)d_in[4];
    const float* iw2 = (const float*)d_in[5];
    const float* rw2 = (const float*)d_in[6];
    const float* b2  = (const float*)d_in[7];
    float* out = (float*)d_out;

    int N = in_sizes[0] / 256;
    long long E = in_sizes[1] / 2;
    float* hfeat = out + (long long)N * 16;   // agg_feature region of d_out

    const int smem1 = (16384 + 32 * 264) * (int)sizeof(float);  // 99328 B
    cudaFuncSetAttribute(k_gemm1, cudaFuncAttributeMaxDynamicSharedMemorySize, smem1);

    int nbN  = (N + 255) / 256;
    int nbSc = (N + 1023) / 1024;            // scan blocks (<=512)
    int nbE  = (int)((E + 255) / 256);
    int nbG1 = (N * 8 + 255) / 256;
    int nbG2 = (N * 4 + 255) / 256;

    k_zero   <<<nbN, 256>>>(N);
    k_detect <<<1, 32>>>(ei);
    k_prep   <<<(16384 + 1024 + 64 + 255) / 256, 256>>>(iw1, rw1, b1, iw2, rw2, b2);
    k_deg    <<<nbE, 256>>>(ei, E);
    k_dinv   <<<nbN, 256>>>(N);
    k_scanA  <<<nbSc, 256>>>(N);
    k_scanB  <<<1, 512>>>(nbSc);
    k_scanC  <<<nbSc, 256>>>(N);
    k_fill   <<<nbE, 256>>>(ei, E);
    k_gemm1  <<<(N + 31) / 32, 256, smem1>>>(x, N);
    k_gather1<<<nbG1, 256>>>(hfeat, N);
    k_gather2<<<nbG2, 256>>>(hfeat, N);
    k_final  <<<nbN, 256>>>(hfeat, out, N);
}

// round 7
// speedup vs baseline: 2.5281x; 2.0520x over previous
#include <cuda_runtime.h>

// Problem constants: N=100000, E=3200000, F_IN=256, HID=16, C=16, K=2
#define MAXN 131072
#define MAXE 3200000

// ---------------- device scratch ----------------
__device__ int   g_is64;
__device__ int   g_deg [MAXN];
__device__ int   g_off [MAXN];
__device__ int   g_cur [MAXN];
__device__ int   g_bsum[512];
__device__ int   g_boff[512];
__device__ float g_dinv[MAXN];
__device__ float g_h1  [MAXN * 32];   // conv1 init features, later scaled by dinv[src]
__device__ float g_agg1[MAXN * 32];   // conv1 root+bias (accumulator init)
__device__ float g_hfs [MAXN * 16];   // hfeat * dinv (source side for gather2)
__device__ float g_aggr[MAXN * 16];   // conv2 raw aggregation
__device__ float g_W1  [256 * 64];    // cols 0..31 = init (k0,k1), 32..63 = root
__device__ float g_W2  [16 * 64];
__device__ float g_b1  [32];
__device__ float g_b2  [32];
__device__ int   g_csrs[MAXE];        // dst-sorted src ids

// ---------------- zero degree + edge-dtype detect ----------------
__global__ void k_zerodetect(const int* __restrict__ ei, int n) {
    int i = blockIdx.x * 256 + threadIdx.x;
    if (i < n) g_deg[i] = 0;
    if (i == 0) {
        int ok = 1;
        #pragma unroll 1
        for (int j = 0; j < 64; j++)
            if (ei[2 * j + 1] != 0) { ok = 0; break; }
        g_is64 = ok;
    }
}

// pack weights:  g_W1[f*64 + k*16 + o] = init_w1[k][f][o];  +32 for root
__global__ void k_prep(const float* __restrict__ iw1, const float* __restrict__ rw1,
                       const float* __restrict__ b1,
                       const float* __restrict__ iw2, const float* __restrict__ rw2,
                       const float* __restrict__ b2) {
    int i = blockIdx.x * 256 + threadIdx.x;
    if (i < 16384) {
        int f = i >> 6, c = i & 63;
        if (c < 32) { int k = c >> 4, o = c & 15; g_W1[i] = iw1[k * 4096 + f * 16 + o]; }
        else        { int cc = c - 32; int k = cc >> 4, o = cc & 15; g_W1[i] = rw1[k * 4096 + f * 16 + o]; }
    } else if (i < 16384 + 1024) {
        int j = i - 16384;
        int f = j >> 6, c = j & 63;
        if (c < 32) { int k = c >> 4, o = c & 15; g_W2[j] = iw2[k * 256 + f * 16 + o]; }
        else        { int cc = c - 32; int k = cc >> 4, o = cc & 15; g_W2[j] = rw2[k * 256 + f * 16 + o]; }
    } else if (i < 16384 + 1024 + 32) {
        int j = i - 16384 - 1024; g_b1[j] = b1[j];
    } else if (i < 16384 + 1024 + 64) {
        int j = i - 16384 - 1024 - 32; g_b2[j] = b2[j];
    }
}

__global__ void k_deg(const int* __restrict__ ei, long long E) {
    long long t = blockIdx.x * 256LL + threadIdx.x;
    if (t >= E) return;
    long long pos = E + t;                 // dst index
    int d = g_is64 ? ei[pos << 1] : ei[pos];
    atomicAdd(&g_deg[d], 1);
}

// ---------------- GEMM1: x[N,256] @ W1[256,64], register-tiled ----------------
// Block: 256 threads, tile 128 rows x 64 cols. Thread (ty=tid>>3, tx=tid&7)
// computes rows ty*4..+3, cols tx*8..+7 (4x8 = 32 accs). K chunked by 32.
__global__ void __launch_bounds__(256, 3) k_gemm1(const float* __restrict__ x, int nNodes) {
    __shared__ float sxT[32][132];   // [k][row], padded
    __shared__ float sw [32][64];    // [k][col]
    int tid = threadIdx.x;
    int base = blockIdx.x * 128;
    int tx = tid & 7, ty = tid >> 3;

    float acc[4][8];
    #pragma unroll
    for (int i = 0; i < 4; i++)
        #pragma unroll
        for (int j = 0; j < 8; j++) acc[i][j] = 0.f;

    int lr  = tid >> 3;   // 0..31
    int lc4 = tid & 7;    // float4 col within 32-chunk

    for (int kk = 0; kk < 8; kk++) {
        // W chunk: 32x64 floats = 512 float4
        #pragma unroll
        for (int i = 0; i < 2; i++) {
            int flat = tid + i * 256;              // float4 index
            int k = flat >> 4, c4 = flat & 15;
            float4 w = *reinterpret_cast<const float4*>(g_W1 + (kk * 32 + k) * 64 + c4 * 4);
            *reinterpret_cast<float4*>(&sw[k][c4 * 4]) = w;
        }
        // X chunk transposed: rows base..base+127, cols kk*32..+31
        #pragma unroll
        for (int q = 0; q < 4; q++) {
            int r = lr + q * 32;
            int n = base + r;
            float4 v = make_float4(0.f, 0.f, 0.f, 0.f);
            if (n < nNodes)
                v = *reinterpret_cast<const float4*>(x + (long long)n * 256 + kk * 32 + lc4 * 4);
            sxT[lc4 * 4 + 0][r] = v.x;
            sxT[lc4 * 4 + 1][r] = v.y;
            sxT[lc4 * 4 + 2][r] = v.z;
            sxT[lc4 * 4 + 3][r] = v.w;
        }
        __syncthreads();
        #pragma unroll
        for (int k = 0; k < 32; k++) {
            float4 xv = *reinterpret_cast<const float4*>(&sxT[k][ty * 4]);
            float4 w0 = *reinterpret_cast<const float4*>(&sw[k][tx * 8]);
            float4 w1 = *reinterpret_cast<const float4*>(&sw[k][tx * 8 + 4]);
            float xs[4] = {xv.x, xv.y, xv.z, xv.w};
            float ws[8] = {w0.x, w0.y, w0.z, w0.w, w1.x, w1.y, w1.z, w1.w};
            #pragma unroll
            for (int i = 0; i < 4; i++)
                #pragma unroll
                for (int j = 0; j < 8; j++)
                    acc[i][j] += xs[i] * ws[j];
        }
        __syncthreads();
    }

    // epilogue
    int c = tx * 8;
    #pragma unroll
    for (int i = 0; i < 4; i++) {
        int n = base + ty * 4 + i;
        if (n >= nNodes) break;
        if (c < 32) {
            float4* o = reinterpret_cast<float4*>(g_h1 + (long long)n * 32 + c);
            o[0] = make_float4(acc[i][0], acc[i][1], acc[i][2], acc[i][3]);
            o[1] = make_float4(acc[i][4], acc[i][5], acc[i][6], acc[i][7]);
        } else {
            int cc = c - 32;
            float4* o = reinterpret_cast<float4*>(g_agg1 + (long long)n * 32 + cc);
            o[0] = make_float4(acc[i][0] + g_b1[cc],     acc[i][1] + g_b1[cc + 1],
                               acc[i][2] + g_b1[cc + 2], acc[i][3] + g_b1[cc + 3]);
            o[1] = make_float4(acc[i][4] + g_b1[cc + 4], acc[i][5] + g_b1[cc + 5],
                               acc[i][6] + g_b1[cc + 6], acc[i][7] + g_b1[cc + 7]);
        }
    }
}

// ---------------- 3-phase exclusive scan of g_deg -> g_off/g_cur (+dinv) ----
__global__ void k_scanA(int n) {
    __shared__ int sm[256];
    int base = blockIdx.x * 1024;
    int t = threadIdx.x;
    int s = 0;
    #pragma unroll
    for (int j = 0; j < 4; j++) {
        int i = base + t * 4 + j;
        if (i < n) s += g_deg[i];
    }
    sm[t] = s; __syncthreads();
    #pragma unroll
    for (int o = 128; o > 0; o >>= 1) {
        if (t < o) sm[t] += sm[t + o];
        __syncthreads();
    }
    if (t == 0) g_bsum[blockIdx.x] = sm[0];
}
__global__ void k_scanB(int nb) {
    __shared__ int sm[512];
    int t = threadIdx.x;
    int v0 = (t < nb) ? g_bsum[t] : 0;
    sm[t] = v0; __syncthreads();
    #pragma unroll
    for (int o = 1; o < 512; o <<= 1) {
        int v = (t >= o) ? sm[t - o] : 0;
        __syncthreads();
        sm[t] += v;
        __syncthreads();
    }
    if (t < nb) g_boff[t] = sm[t] - v0;    // exclusive
}
__global__ void k_scanC(int n) {
    __shared__ int sm[256];
    int base = blockIdx.x * 1024;
    int t = threadIdx.x;
    int d[4]; int s = 0;
    #pragma unroll
    for (int j = 0; j < 4; j++) {
        int i = base + t * 4 + j;
        d[j] = (i < n) ? g_deg[i] : 0;
        s += d[j];
    }
    sm[t] = s; __syncthreads();
    #pragma unroll
    for (int o = 1; o < 256; o <<= 1) {
        int v = (t >= o) ? sm[t - o] : 0;
        __syncthreads();
        sm[t] += v;
        __syncthreads();
    }
    int excl = sm[t] - s + g_boff[blockIdx.x];
    #pragma unroll
    for (int j = 0; j < 4; j++) {
        int i = base + t * 4 + j;
        if (i < n) {
            g_off[i] = excl; g_cur[i] = excl; excl += d[j];
            g_dinv[i] = (d[j] > 0) ? rsqrtf((float)d[j]) : 0.0f;
        }
    }
}

// ---------------- fill CSR (src only, 4B/edge) ----------------
__global__ void k_fill(const int* __restrict__ ei, long long E) {
    long long t = blockIdx.x * 256LL + threadIdx.x;
    if (t >= E) return;
    int is64 = g_is64;
    int s = is64 ? ei[t << 1] : ei[t];
    long long dp = E + t;
    int d = is64 ? ei[dp << 1] : ei[dp];
    int pos = atomicAdd(&g_cur[d], 1);
    g_csrs[pos] = s;
}

// ---------------- scale h1 rows by dinv[src] (in place) ----------------
__global__ void k_scale(int nNodes) {
    int t = blockIdx.x * 256 + threadIdx.x;
    if (t >= nNodes * 8) return;
    int n = t >> 3, part = t & 7;
    float s = g_dinv[n];
    float4* p = reinterpret_cast<float4*>(g_h1 + ((long long)n << 5) + (part << 2));
    float4 v = *p;
    *p = make_float4(v.x * s, v.y * s, v.z * s, v.w * s);
}

// ---------------- gather1: acc = dinv[n]*sum(h1s[src]); +root+bias; relu; mean --
// 8 lanes/node (4 cols each); k0/k1 combined via shfl_xor(4).
__global__ void __launch_bounds__(256) k_gather1(float* __restrict__ hfeat, int nNodes) {
    int t = blockIdx.x * 256 + threadIdx.x;
    int node = t >> 3;
    bool valid = node < nNodes;
    int n = valid ? node : (nNodes - 1);
    int part = t & 7;
    int beg = g_off[n];
    int end = beg + g_deg[n];
    float4 rb = *reinterpret_cast<const float4*>(g_agg1 + ((long long)n << 5) + (part << 2));
    float din = g_dinv[n];
    float4 acc = make_float4(0.f, 0.f, 0.f, 0.f);
    int i = beg;
    for (; i + 4 <= end; i += 4) {
        int s0 = g_csrs[i], s1 = g_csrs[i + 1], s2 = g_csrs[i + 2], s3 = g_csrs[i + 3];
        float4 v0 = *reinterpret_cast<const float4*>(g_h1 + ((long long)s0 << 5) + (part << 2));
        float4 v1 = *reinterpret_cast<const float4*>(g_h1 + ((long long)s1 << 5) + (part << 2));
        float4 v2 = *reinterpret_cast<const float4*>(g_h1 + ((long long)s2 << 5) + (part << 2));
        float4 v3 = *reinterpret_cast<const float4*>(g_h1 + ((long long)s3 << 5) + (part << 2));
        acc.x += v0.x + v1.x + v2.x + v3.x;
        acc.y += v0.y + v1.y + v2.y + v3.y;
        acc.z += v0.z + v1.z + v2.z + v3.z;
        acc.w += v0.w + v1.w + v2.w + v3.w;
    }
    for (; i < end; i++) {
        int s = g_csrs[i];
        float4 v = *reinterpret_cast<const float4*>(g_h1 + ((long long)s << 5) + (part << 2));
        acc.x += v.x; acc.y += v.y; acc.z += v.z; acc.w += v.w;
    }
    acc.x = fmaxf(rb.x + din * acc.x, 0.f);
    acc.y = fmaxf(rb.y + din * acc.y, 0.f);
    acc.z = fmaxf(rb.z + din * acc.z, 0.f);
    acc.w = fmaxf(rb.w + din * acc.w, 0.f);
    float ox = 0.5f * (acc.x + __shfl_xor_sync(0xffffffffu, acc.x, 4));
    float oy = 0.5f * (acc.y + __shfl_xor_sync(0xffffffffu, acc.y, 4));
    float oz = 0.5f * (acc.z + __shfl_xor_sync(0xffffffffu, acc.z, 4));
    float ow = 0.5f * (acc.w + __shfl_xor_sync(0xffffffffu, acc.w, 4));
    if (valid && part < 4) {
        reinterpret_cast<float4*>(hfeat)[((long long)n << 2) + part] =
            make_float4(ox, oy, oz, ow);
        reinterpret_cast<float4*>(g_hfs)[((long long)n << 2) + part] =
            make_float4(ox * din, oy * din, oz * din, ow * din);
    }
}

// ---------------- gather2: aggr[n] = dinv[n] * sum(hfs[src]) ----------------
__global__ void __launch_bounds__(256) k_gather2(int nNodes) {
    int t = blockIdx.x * 256 + threadIdx.x;
    int n = t >> 2;
    if (n >= nNodes) return;
    int part = t & 3;
    int beg = g_off[n];
    int end = beg + g_deg[n];
    float din = g_dinv[n];
    float4 acc = make_float4(0.f, 0.f, 0.f, 0.f);
    int i = beg;
    for (; i + 4 <= end; i += 4) {
        int s0 = g_csrs[i], s1 = g_csrs[i + 1], s2 = g_csrs[i + 2], s3 = g_csrs[i + 3];
        float4 v0 = *reinterpret_cast<const float4*>(g_hfs + ((long long)s0 << 4) + (part << 2));
        float4 v1 = *reinterpret_cast<const float4*>(g_hfs + ((long long)s1 << 4) + (part << 2));
        float4 v2 = *reinterpret_cast<const float4*>(g_hfs + ((long long)s2 << 4) + (part << 2));
        float4 v3 = *reinterpret_cast<const float4*>(g_hfs + ((long long)s3 << 4) + (part << 2));
        acc.x += v0.x + v1.x + v2.x + v3.x;
        acc.y += v0.y + v1.y + v2.y + v3.y;
        acc.z += v0.z + v1.z + v2.z + v3.z;
        acc.w += v0.w + v1.w + v2.w + v3.w;
    }
    for (; i < end; i++) {
        int s = g_csrs[i];
        float4 v = *reinterpret_cast<const float4*>(g_hfs + ((long long)s << 4) + (part << 2));
        acc.x += v.x; acc.y += v.y; acc.z += v.z; acc.w += v.w;
    }
    reinterpret_cast<float4*>(g_aggr)[((long long)n << 2) + part] =
        make_float4(acc.x * din, acc.y * din, acc.z * din, acc.w * din);
}

// ---------------- final: GEMM2 + root + bias, K-mean, log_softmax ----------------
__global__ void __launch_bounds__(256) k_final(const float* __restrict__ hfeat,
                                               float* __restrict__ out, int nNodes) {
    __shared__ float sw[1024];
    __shared__ float sb[32];
    for (int i = threadIdx.x; i < 1024; i += 256) sw[i] = g_W2[i];
    if (threadIdx.x < 32) sb[threadIdx.x] = g_b2[threadIdx.x];
    __syncthreads();
    int n = blockIdx.x * 256 + threadIdx.x;
    if (n >= nNodes) return;

    float hr[16], ag[16];
    const float4* hp = reinterpret_cast<const float4*>(hfeat + (long long)n * 16);
    const float4* ap = reinterpret_cast<const float4*>(g_aggr) + (long long)n * 4;
    #pragma unroll
    for (int j = 0; j < 4; j++) {
        float4 h4 = hp[j], a4 = ap[j];
        hr[4 * j] = h4.x; hr[4 * j + 1] = h4.y; hr[4 * j + 2] = h4.z; hr[4 * j + 3] = h4.w;
        ag[4 * j] = a4.x; ag[4 * j + 1] = a4.y; ag[4 * j + 2] = a4.z; ag[4 * j + 3] = a4.w;
    }

    float l[16];
    #pragma unroll
    for (int o = 0; o < 16; o++) l[o] = 0.f;
    #pragma unroll
    for (int k = 0; k < 2; k++) {
        float acc[16];
        #pragma unroll
        for (int o = 0; o < 16; o++) acc[o] = sb[k * 16 + o];
        #pragma unroll
        for (int f = 0; f < 16; f++) {
            float av = ag[f], hv = hr[f];
            const float* wi = sw + f * 64 + k * 16;       // init
            const float* wr = wi + 32;                    // root
            #pragma unroll
            for (int o = 0; o < 16; o++)
                acc[o] += av * wi[o] + hv * wr[o];
        }
        #pragma unroll
        for (int o = 0; o < 16; o++) l[o] += 0.5f * acc[o];
    }

    float m = l[0];
    #pragma unroll
    for (int i = 1; i < 16; i++) m = fmaxf(m, l[i]);
    float s = 0.f;
    #pragma unroll
    for (int i = 0; i < 16; i++) s += expf(l[i] - m);
    float lg = m + logf(s);
    float4* o4 = reinterpret_cast<float4*>(out + (long long)n * 16);
    #pragma unroll
    for (int j = 0; j < 4; j++)
        o4[j] = make_float4(l[4 * j] - lg, l[4 * j + 1] - lg,
                            l[4 * j + 2] - lg, l[4 * j + 3] - lg);
}

// ---------------- launch ----------------
extern "C" void kernel_launch(void* const* d_in, const int* in_sizes, int n_in,
                              void* d_out, int out_size) {
    const float* x   = (const float*)d_in[0];
    const int*   ei  = (const int*)d_in[1];
    const float* iw1 = (const float*)d_in[2];
    const float* rw1 = (const float*)d_in[3];
    const float* b1  = (const float*)d_in[4];
    const float* iw2 = (const float*)d_in[5];
    const float* rw2 = (const float*)d_in[6];
    const float* b2  = (const float*)d_in[7];
    float* out = (float*)d_out;

    int N = in_sizes[0] / 256;
    long long E = in_sizes[1] / 2;
    float* hfeat = out + (long long)N * 16;   // agg_feature region of d_out

    int nbN  = (N + 255) / 256;
    int nbSc = (N + 1023) / 1024;
    int nbE  = (int)((E + 255) / 256);
    int nbG1 = (N * 8 + 255) / 256;
    int nbG2 = (N * 4 + 255) / 256;

    k_zerodetect<<<nbN, 256>>>(ei, N);
    k_prep   <<<(16384 + 1024 + 64 + 255) / 256, 256>>>(iw1, rw1, b1, iw2, rw2, b2);
    k_deg    <<<nbE, 256>>>(ei, E);
    k_gemm1  <<<(N + 127) / 128, 256>>>(x, N);       // launch idx 3 -> profiled
    k_scanA  <<<nbSc, 256>>>(N);
    k_scanB  <<<1, 512>>>(nbSc);
    k_scanC  <<<nbSc, 256>>>(N);
    k_fill   <<<nbE, 256>>>(ei, E);
    k_scale  <<<nbG1, 256>>>(N);
    k_gather1<<<nbG1, 256>>>(hfeat, N);
    k_gather2<<<nbG2, 256>>>(N);
    k_final  <<<nbN, 256>>>(hfeat, out, N);
}

// round 11
// speedup vs baseline: 2.5508x; 1.0090x over previous
#include <cuda_runtime.h>

// Problem constants: N=100000, E=3200000, F_IN=256, HID=16, C=16, K=2
#define MAXN 131072
#define MAXE 3200000

// packed f32x2 FMA (FFMA2) — ptxas never emits this from C++, PTX only
#define FMA_F32X2(d, a, b, c) \
    asm("fma.rn.f32x2 %0, %1, %2, %3;" : "=l"(d) : "l"(a), "l"(b), "l"(c))
#define PACK_F32X2(out, lo, hi) \
    asm("mov.b64 %0, {%1, %2};" : "=l"(out) : "f"(lo), "f"(hi))
#define UNPACK_F32X2(lo, hi, in) \
    asm("mov.b64 {%0, %1}, %2;" : "=f"(lo), "=f"(hi) : "l"(in))

// ---------------- device scratch ----------------
__device__ int   g_is64;
__device__ int   g_deg [MAXN];
__device__ int   g_off [MAXN];
__device__ int   g_cur [MAXN];
__device__ int   g_bsum[512];
__device__ int   g_boff[512];
__device__ float g_dinv[MAXN];
__device__ float g_h1  [MAXN * 32];   // conv1 init features, pre-scaled by dinv[src]
__device__ float g_agg1[MAXN * 32];   // conv1 root+bias (accumulator init)
__device__ float g_hfs [MAXN * 16];   // hfeat * dinv (source side for gather2)
__device__ float g_aggr[MAXN * 16];   // conv2 raw aggregation
__device__ float g_W1  [256 * 64];    // cols 0..31 = init (k0,k1), 32..63 = root
__device__ float g_W2  [16 * 64];
__device__ float g_b1  [32];
__device__ float g_b2  [32];
__device__ int   g_csrs[MAXE];        // dst-sorted src ids

// ---------------- merged: zero deg + dtype detect + weight packing ----------
__global__ void k_prepzero(const int* __restrict__ ei, int n,
                           const float* __restrict__ iw1, const float* __restrict__ rw1,
                           const float* __restrict__ b1,
                           const float* __restrict__ iw2, const float* __restrict__ rw2,
                           const float* __restrict__ b2) {
    int i = blockIdx.x * 256 + threadIdx.x;
    if (i < n) g_deg[i] = 0;
    if (i == 0) {
        int ok = 1;
        #pragma unroll 1
        for (int j = 0; j < 64; j++)
            if (ei[2 * j + 1] != 0) { ok = 0; break; }
        g_is64 = ok;
    }
    if (i < 16384) {
        int f = i >> 6, c = i & 63;
        if (c < 32) { int k = c >> 4, o = c & 15; g_W1[i] = iw1[k * 4096 + f * 16 + o]; }
        else        { int cc = c - 32; int k = cc >> 4, o = cc & 15; g_W1[i] = rw1[k * 4096 + f * 16 + o]; }
    } else if (i < 16384 + 1024) {
        int j = i - 16384;
        int f = j >> 6, c = j & 63;
        if (c < 32) { int k = c >> 4, o = c & 15; g_W2[j] = iw2[k * 256 + f * 16 + o]; }
        else        { int cc = c - 32; int k = cc >> 4, o = cc & 15; g_W2[j] = rw2[k * 256 + f * 16 + o]; }
    } else if (i < 16384 + 1024 + 32) {
        int j = i - 16384 - 1024; g_b1[j] = b1[j];
    } else if (i < 16384 + 1024 + 64) {
        int j = i - 16384 - 1024 - 32; g_b2[j] = b2[j];
    }
}

__global__ void k_deg(const int* __restrict__ ei, long long E) {
    long long t = blockIdx.x * 256LL + threadIdx.x;
    if (t >= E) return;
    long long pos = E + t;                 // dst index
    int d = g_is64 ? ei[pos << 1] : ei[pos];
    atomicAdd(&g_deg[d], 1);
}

__global__ void k_dinv(int n) {
    int i = blockIdx.x * 256 + threadIdx.x;
    if (i >= n) return;
    int d = g_deg[i];
    g_dinv[i] = (d > 0) ? rsqrtf((float)d) : 0.0f;
}

// ---------------- GEMM1: x[N,256] @ W1[256,64], reg-tiled + FFMA2 -------------
// Block 256 thr, tile 128 rows x 64 cols. Thread (ty,tx): rows ty*4..+3,
// cols tx*8..+7 held as 4x4 f32x2 pairs. Init cols pre-scaled by dinv[row].
__global__ void __launch_bounds__(256, 3) k_gemm1(const float* __restrict__ x, int nNodes) {
    __shared__ float sxT[32][132];   // [k][row], padded
    __shared__ float sw [32][64];    // [k][col]
    int tid = threadIdx.x;
    int base = blockIdx.x * 128;
    int tx = tid & 7, ty = tid >> 3;

    unsigned long long acc2[4][4];
    #pragma unroll
    for (int i = 0; i < 4; i++)
        #pragma unroll
        for (int j = 0; j < 4; j++) acc2[i][j] = 0ULL;

    int lr  = tid >> 3;   // 0..31
    int lc4 = tid & 7;    // float4 col within 32-chunk

    for (int kk = 0; kk < 8; kk++) {
        // W chunk: 32x64 floats = 512 float4
        #pragma unroll
        for (int i = 0; i < 2; i++) {
            int flat = tid + i * 256;              // float4 index
            int k = flat >> 4, c4 = flat & 15;
            float4 w = *reinterpret_cast<const float4*>(g_W1 + (kk * 32 + k) * 64 + c4 * 4);
            *reinterpret_cast<float4*>(&sw[k][c4 * 4]) = w;
        }
        // X chunk transposed: rows base..base+127, cols kk*32..+31
        #pragma unroll
        for (int q = 0; q < 4; q++) {
            int r = lr + q * 32;
            int n = base + r;
            float4 v = make_float4(0.f, 0.f, 0.f, 0.f);
            if (n < nNodes)
                v = *reinterpret_cast<const float4*>(x + (long long)n * 256 + kk * 32 + lc4 * 4);
            sxT[lc4 * 4 + 0][r] = v.x;
            sxT[lc4 * 4 + 1][r] = v.y;
            sxT[lc4 * 4 + 2][r] = v.z;
            sxT[lc4 * 4 + 3][r] = v.w;
        }
        __syncthreads();
        #pragma unroll
        for (int k = 0; k < 32; k++) {
            float4 xv = *reinterpret_cast<const float4*>(&sxT[k][ty * 4]);
            ulonglong2 wa = *reinterpret_cast<const ulonglong2*>(&sw[k][tx * 8]);
            ulonglong2 wb = *reinterpret_cast<const ulonglong2*>(&sw[k][tx * 8 + 4]);
            float xs[4] = {xv.x, xv.y, xv.z, xv.w};
            #pragma unroll
            for (int i = 0; i < 4; i++) {
                unsigned long long xp;
                PACK_F32X2(xp, xs[i], xs[i]);
                FMA_F32X2(acc2[i][0], xp, wa.x, acc2[i][0]);
                FMA_F32X2(acc2[i][1], xp, wa.y, acc2[i][1]);
                FMA_F32X2(acc2[i][2], xp, wb.x, acc2[i][2]);
                FMA_F32X2(acc2[i][3], xp, wb.y, acc2[i][3]);
            }
        }
        __syncthreads();
    }

    // epilogue: unpack; init cols scaled by dinv[row]; root cols + bias
    int c = tx * 8;
    #pragma unroll
    for (int i = 0; i < 4; i++) {
        int n = base + ty * 4 + i;
        if (n >= nNodes) break;
        float a[8];
        #pragma unroll
        for (int j = 0; j < 4; j++) UNPACK_F32X2(a[2 * j], a[2 * j + 1], acc2[i][j]);
        if (c < 32) {
            float s = g_dinv[n];
            float4* o = reinterpret_cast<float4*>(g_h1 + (long long)n * 32 + c);
            o[0] = make_float4(a[0] * s, a[1] * s, a[2] * s, a[3] * s);
            o[1] = make_float4(a[4] * s, a[5] * s, a[6] * s, a[7] * s);
        } else {
            int cc = c - 32;
            float4* o = reinterpret_cast<float4*>(g_agg1 + (long long)n * 32 + cc);
            o[0] = make_float4(a[0] + g_b1[cc],     a[1] + g_b1[cc + 1],
                               a[2] + g_b1[cc + 2], a[3] + g_b1[cc + 3]);
            o[1] = make_float4(a[4] + g_b1[cc + 4], a[5] + g_b1[cc + 5],
                               a[6] + g_b1[cc + 6], a[7] + g_b1[cc + 7]);
        }
    }
}

// ---------------- 3-phase exclusive scan of g_deg -> g_off/g_cur ----------
__global__ void k_scanA(int n) {
    __shared__ int sm[256];
    int base = blockIdx.x * 1024;
    int t = threadIdx.x;
    int s = 0;
    #pragma unroll
    for (int j = 0; j < 4; j++) {
        int i = base + t * 4 + j;
        if (i < n) s += g_deg[i];
    }
    sm[t] = s; __syncthreads();
    #pragma unroll
    for (int o = 128; o > 0; o >>= 1) {
        if (t < o) sm[t] += sm[t + o];
        __syncthreads();
    }
    if (t == 0) g_bsum[blockIdx.x] = sm[0];
}
__global__ void k_scanB(int nb) {
    __shared__ int sm[512];
    int t = threadIdx.x;
    int v0 = (t < nb) ? g_bsum[t] : 0;
    sm[t] = v0; __syncthreads();
    #pragma unroll
    for (int o = 1; o < 512; o <<= 1) {
        int v = (t >= o) ? sm[t - o] : 0;
        __syncthreads();
        sm[t] += v;
        __syncthreads();
    }
    if (t < nb) g_boff[t] = sm[t] - v0;    // exclusive
}
__global__ void k_scanC(int n) {
    __shared__ int sm[256];
    int base = blockIdx.x * 1024;
    int t = threadIdx.x;
    int d[4]; int s = 0;
    #pragma unroll
    for (int j = 0; j < 4; j++) {
        int i = base + t * 4 + j;
        d[j] = (i < n) ? g_deg[i] : 0;
        s += d[j];
    }
    sm[t] = s; __syncthreads();
    #pragma unroll
    for (int o = 1; o < 256; o <<= 1) {
        int v = (t >= o) ? sm[t - o] : 0;
        __syncthreads();
        sm[t] += v;
        __syncthreads();
    }
    int excl = sm[t] - s + g_boff[blockIdx.x];
    #pragma unroll
    for (int j = 0; j < 4; j++) {
        int i = base + t * 4 + j;
        if (i < n) { g_off[i] = excl; g_cur[i] = excl; excl += d[j]; }
    }
}

// ---------------- fill CSR (src only, 4B/edge) ----------------
__global__ void k_fill(const int* __restrict__ ei, long long E) {
    long long t = blockIdx.x * 256LL + threadIdx.x;
    if (t >= E) return;
    int is64 = g_is64;
    int s = is64 ? ei[t << 1] : ei[t];
    long long dp = E + t;
    int d = is64 ? ei[dp << 1] : ei[dp];
    int pos = atomicAdd(&g_cur[d], 1);
    g_csrs[pos] = s;
}

// ---------------- gather1: acc = dinv[n]*sum(h1[src]); +root+bias; relu; mean --
// 8 lanes/node (4 cols each); k0/k1 combined via shfl_xor(4).
__global__ void __launch_bounds__(256) k_gather1(float* __restrict__ hfeat, int nNodes) {
    int t = blockIdx.x * 256 + threadIdx.x;
    int node = t >> 3;
    bool valid = node < nNodes;
    int n = valid ? node : (nNodes - 1);
    int part = t & 7;
    int beg = g_off[n];
    int end = beg + g_deg[n];
    float4 rb = *reinterpret_cast<const float4*>(g_agg1 + ((long long)n << 5) + (part << 2));
    float din = g_dinv[n];
    float4 acc = make_float4(0.f, 0.f, 0.f, 0.f);
    int i = beg;
    for (; i + 4 <= end; i += 4) {
        int s0 = g_csrs[i], s1 = g_csrs[i + 1], s2 = g_csrs[i + 2], s3 = g_csrs[i + 3];
        float4 v0 = *reinterpret_cast<const float4*>(g_h1 + ((long long)s0 << 5) + (part << 2));
        float4 v1 = *reinterpret_cast<const float4*>(g_h1 + ((long long)s1 << 5) + (part << 2));
        float4 v2 = *reinterpret_cast<const float4*>(g_h1 + ((long long)s2 << 5) + (part << 2));
        float4 v3 = *reinterpret_cast<const float4*>(g_h1 + ((long long)s3 << 5) + (part << 2));
        acc.x += v0.x + v1.x + v2.x + v3.x;
        acc.y += v0.y + v1.y + v2.y + v3.y;
        acc.z += v0.z + v1.z + v2.z + v3.z;
        acc.w += v0.w + v1.w + v2.w + v3.w;
    }
    for (; i < end; i++) {
        int s = g_csrs[i];
        float4 v = *reinterpret_cast<const float4*>(g_h1 + ((long long)s << 5) + (part << 2));
        acc.x += v.x; acc.y += v.y; acc.z += v.z; acc.w += v.w;
    }
    acc.x = fmaxf(rb.x + din * acc.x, 0.f);
    acc.y = fmaxf(rb.y + din * acc.y, 0.f);
    acc.z = fmaxf(rb.z + din * acc.z, 0.f);
    acc.w = fmaxf(rb.w + din * acc.w, 0.f);
    float ox = 0.5f * (acc.x + __shfl_xor_sync(0xffffffffu, acc.x, 4));
    float oy = 0.5f * (acc.y + __shfl_xor_sync(0xffffffffu, acc.y, 4));
    float oz = 0.5f * (acc.z + __shfl_xor_sync(0xffffffffu, acc.z, 4));
    float ow = 0.5f * (acc.w + __shfl_xor_sync(0xffffffffu, acc.w, 4));
    if (valid && part < 4) {
        reinterpret_cast<float4*>(hfeat)[((long long)n << 2) + part] =
            make_float4(ox, oy, oz, ow);
        reinterpret_cast<float4*>(g_hfs)[((long long)n << 2) + part] =
            make_float4(ox * din, oy * din, oz * din, ow * din);
    }
}

// ---------------- gather2: aggr[n] = dinv[n] * sum(hfs[src]) ----------------
__global__ void __launch_bounds__(256) k_gather2(int nNodes) {
    int t = blockIdx.x * 256 + threadIdx.x;
    int n = t >> 2;
    if (n >= nNodes) return;
    int part = t & 3;
    int beg = g_off[n];
    int end = beg + g_deg[n];
    float din = g_dinv[n];
    float4 acc = make_float4(0.f, 0.f, 0.f, 0.f);
    int i = beg;
    for (; i + 4 <= end; i += 4) {
        int s0 = g_csrs[i], s1 = g_csrs[i + 1], s2 = g_csrs[i + 2], s3 = g_csrs[i + 3];
        float4 v0 = *reinterpret_cast<const float4*>(g_hfs + ((long long)s0 << 4) + (part << 2));
        float4 v1 = *reinterpret_cast<const float4*>(g_hfs + ((long long)s1 << 4) + (part << 2));
        float4 v2 = *reinterpret_cast<const float4*>(g_hfs + ((long long)s2 << 4) + (part << 2));
        float4 v3 = *reinterpret_cast<const float4*>(g_hfs + ((long long)s3 << 4) + (part << 2));
        acc.x += v0.x + v1.x + v2.x + v3.x;
        acc.y += v0.y + v1.y + v2.y + v3.y;
        acc.z += v0.z + v1.z + v2.z + v3.z;
        acc.w += v0.w + v1.w + v2.w + v3.w;
    }
    for (; i < end; i++) {
        int s = g_csrs[i];
        float4 v = *reinterpret_cast<const float4*>(g_hfs + ((long long)s << 4) + (part << 2));
        acc.x += v.x; acc.y += v.y; acc.z += v.z; acc.w += v.w;
    }
    reinterpret_cast<float4*>(g_aggr)[((long long)n << 2) + part] =
        make_float4(acc.x * din, acc.y * din, acc.z * din, acc.w * din);
}

// ---------------- final: GEMM2 + root + bias, K-mean, log_softmax ----------------
__global__ void __launch_bounds__(256) k_final(const float* __restrict__ hfeat,
                                               float* __restrict__ out, int nNodes) {
    __shared__ float sw[1024];
    __shared__ float sb[32];
    for (int i = threadIdx.x; i < 1024; i += 256) sw[i] = g_W2[i];
    if (threadIdx.x < 32) sb[threadIdx.x] = g_b2[threadIdx.x];
    __syncthreads();
    int n = blockIdx.x * 256 + threadIdx.x;
    if (n >= nNodes) return;

    float hr[16], ag[16];
    const float4* hp = reinterpret_cast<const float4*>(hfeat + (long long)n * 16);
    const float4* ap = reinterpret_cast<const float4*>(g_aggr) + (long long)n * 4;
    #pragma unroll
    for (int j = 0; j < 4; j++) {
        float4 h4 = hp[j], a4 = ap[j];
        hr[4 * j] = h4.x; hr[4 * j + 1] = h4.y; hr[4 * j + 2] = h4.z; hr[4 * j + 3] = h4.w;
        ag[4 * j] = a4.x; ag[4 * j + 1] = a4.y; ag[4 * j + 2] = a4.z; ag[4 * j + 3] = a4.w;
    }

    float l[16];
    #pragma unroll
    for (int o = 0; o < 16; o++) l[o] = 0.f;
    #pragma unroll
    for (int k = 0; k < 2; k++) {
        float acc[16];
        #pragma unroll
        for (int o = 0; o < 16; o++) acc[o] = sb[k * 16 + o];
        #pragma unroll
        for (int f = 0; f < 16; f++) {
            float av = ag[f], hv = hr[f];
            const float* wi = sw + f * 64 + k * 16;       // init
            const float* wr = wi + 32;                    // root
            #pragma unroll
            for (int o = 0; o < 16; o++)
                acc[o] += av * wi[o] + hv * wr[o];
        }
        #pragma unroll
        for (int o = 0; o < 16; o++) l[o] += 0.5f * acc[o];
    }

    float m = l[0];
    #pragma unroll
    for (int i = 1; i < 16; i++) m = fmaxf(m, l[i]);
    float s = 0.f;
    #pragma unroll
    for (int i = 0; i < 16; i++) s += expf(l[i] - m);
    float lg = m + logf(s);
    float4* o4 = reinterpret_cast<float4*>(out + (long long)n * 16);
    #pragma unroll
    for (int j = 0; j < 4; j++)
        o4[j] = make_float4(l[4 * j] - lg, l[4 * j + 1] - lg,
                            l[4 * j + 2] - lg, l[4 * j + 3] - lg);
}

// ---------------- launch ----------------
extern "C" void kernel_launch(void* const* d_in, const int* in_sizes, int n_in,
                              void* d_out, int out_size) {
    const float* x   = (const float*)d_in[0];
    const int*   ei  = (const int*)d_in[1];
    const float* iw1 = (const float*)d_in[2];
    const float* rw1 = (const float*)d_in[3];
    const float* b1  = (const float*)d_in[4];
    const float* iw2 = (const float*)d_in[5];
    const float* rw2 = (const float*)d_in[6];
    const float* b2  = (const float*)d_in[7];
    float* out = (float*)d_out;

    int N = in_sizes[0] / 256;
    long long E = in_sizes[1] / 2;
    float* hfeat = out + (long long)N * 16;   // agg_feature region of d_out

    int nbN  = (N + 255) / 256;
    int nbSc = (N + 1023) / 1024;
    int nbE  = (int)((E + 255) / 256);
    int nbG1 = (N * 8 + 255) / 256;
    int nbG2 = (N * 4 + 255) / 256;
    int nbP  = nbN > ((16384 + 1024 + 64 + 255) / 256) ? nbN : ((16384 + 1024 + 64 + 255) / 256);

    k_prepzero<<<nbP, 256>>>(ei, N, iw1, rw1, b1, iw2, rw2, b2);
    k_deg    <<<nbE, 256>>>(ei, E);
    k_dinv   <<<nbN, 256>>>(N);
    k_gemm1  <<<(N + 127) / 128, 256>>>(x, N);
    k_scanA  <<<nbSc, 256>>>(N);
    k_scanB  <<<1, 512>>>(nbSc);
    k_scanC  <<<nbSc, 256>>>(N);
    k_fill   <<<nbE, 256>>>(ei, E);
    k_gather1<<<nbG1, 256>>>(hfeat, N);
    k_gather2<<<nbG2, 256>>>(N);
    k_final  <<<nbN, 256>>>(hfeat, out, N);
}

// round 13
// speedup vs baseline: 2.5790x; 1.0110x over previous
#include <cuda_runtime.h>

// Problem constants: N=100000, E=3200000, F_IN=256, HID=16, C=16, K=2
#define MAXN 131072
#define MAXE 3200000

// packed f32x2 FMA (FFMA2) — ptxas never emits this from C++, PTX only
#define FMA_F32X2(d, a, b, c) \
    asm("fma.rn.f32x2 %0, %1, %2, %3;" : "=l"(d) : "l"(a), "l"(b), "l"(c))
#define PACK_F32X2(out, lo, hi) \
    asm("mov.b64 %0, {%1, %2};" : "=l"(out) : "f"(lo), "f"(hi))
#define UNPACK_F32X2(lo, hi, in) \
    asm("mov.b64 {%0, %1}, %2;" : "=f"(lo), "=f"(hi) : "l"(in))

// ---------------- device scratch ----------------
__device__ int   g_is64;
__device__ int   g_deg [MAXN];
__device__ int   g_off [MAXN];
__device__ int   g_cur [MAXN];
__device__ int   g_bsum[512];
__device__ int   g_boff[512];
__device__ float g_dinv[MAXN];
__device__ float g_h1  [MAXN * 32];   // conv1 init features, pre-scaled by dinv[src]
__device__ float g_agg1[MAXN * 32];   // conv1 root+bias (accumulator init)
__device__ float g_hfs [MAXN * 16];   // hfeat * dinv (source side for gather2)
__device__ float g_aggr[MAXN * 16];   // conv2 raw aggregation
__device__ float g_W1  [256 * 64];    // cols 0..31 = init (k0,k1), 32..63 = root
__device__ float g_W2  [16 * 64];
__device__ float g_b1  [32];
__device__ float g_b2  [32];
__device__ int   g_csrs[MAXE];        // dst-sorted src ids

// ---------------- merged: zero deg + dtype detect + weight packing ----------
__global__ void k_prepzero(const int* __restrict__ ei, int n,
                           const float* __restrict__ iw1, const float* __restrict__ rw1,
                           const float* __restrict__ b1,
                           const float* __restrict__ iw2, const float* __restrict__ rw2,
                           const float* __restrict__ b2) {
    int i = blockIdx.x * 256 + threadIdx.x;
    if (i < n) g_deg[i] = 0;
    if (i == 0) {
        int ok = 1;
        #pragma unroll 1
        for (int j = 0; j < 64; j++)
            if (ei[2 * j + 1] != 0) { ok = 0; break; }
        g_is64 = ok;
    }
    if (i < 16384) {
        int f = i >> 6, c = i & 63;
        if (c < 32) { int k = c >> 4, o = c & 15; g_W1[i] = iw1[k * 4096 + f * 16 + o]; }
        else        { int cc = c - 32; int k = cc >> 4, o = cc & 15; g_W1[i] = rw1[k * 4096 + f * 16 + o]; }
    } else if (i < 16384 + 1024) {
        int j = i - 16384;
        int f = j >> 6, c = j & 63;
        if (c < 32) { int k = c >> 4, o = c & 15; g_W2[j] = iw2[k * 256 + f * 16 + o]; }
        else        { int cc = c - 32; int k = cc >> 4, o = cc & 15; g_W2[j] = rw2[k * 256 + f * 16 + o]; }
    } else if (i < 16384 + 1024 + 32) {
        int j = i - 16384 - 1024; g_b1[j] = b1[j];
    } else if (i < 16384 + 1024 + 64) {
        int j = i - 16384 - 1024 - 32; g_b2[j] = b2[j];
    }
}

__global__ void k_deg(const int* __restrict__ ei, long long E) {
    long long t = blockIdx.x * 256LL + threadIdx.x;
    if (t >= E) return;
    long long pos = E + t;                 // dst index
    int d = g_is64 ? ei[pos << 1] : ei[pos];
    atomicAdd(&g_deg[d], 1);
}

__global__ void k_dinv(int n) {
    int i = blockIdx.x * 256 + threadIdx.x;
    if (i >= n) return;
    int d = g_deg[i];
    g_dinv[i] = (d > 0) ? rsqrtf((float)d) : 0.0f;
}

// ---------------- GEMM1: x[N,256] @ W1[256,64] -------------------------------
// Reg-tiled 4x8 per thread, FFMA2, XOR-swizzled transpose (conflict-free),
// register double-buffer on x and W chunk loads.
// Swizzle: column group c stores row r at r ^ (((c>>3)&3)<<2).
__global__ void __launch_bounds__(256, 2) k_gemm1(const float* __restrict__ x, int nNodes) {
    __shared__ float sxT[32][132];   // [k][row swizzled], padded
    __shared__ float sw [32][64];    // [k][col]
    int tid = threadIdx.x;
    int base = blockIdx.x * 128;
    int tx = tid & 7, ty = tid >> 3;

    unsigned long long acc2[4][4];
    #pragma unroll
    for (int i = 0; i < 4; i++)
        #pragma unroll
        for (int j = 0; j < 4; j++) acc2[i][j] = 0ULL;

    int lr  = tid >> 3;   // 0..31 (row within x-load slice)
    int lc4 = tid & 7;    // float4 col within 32-chunk

    // swizzle group for this thread's stores: bits 2-3 of row XOR'd by (c>>3)&3,
    // where c = lc4*4..lc4*4+3 -> (c>>3)&3 == lc4>>1 for all 4 j
    int ssw = (lc4 >> 1) << 2;

    // W-load indices (2 float4 per thread per chunk)
    int wk0 = tid >> 4, wc0 = (tid & 15) * 4;          // flat 0..255
    int wk1 = (tid + 256) >> 4, wc1 = wc0;             // flat 256..511

    // ---- prefetch chunk 0 ----
    float4 xr[4];
    float4 wr[2];
    #pragma unroll
    for (int q = 0; q < 4; q++) {
        int n = base + lr + q * 32;
        xr[q] = (n < nNodes) ? *reinterpret_cast<const float4*>(x + (long long)n * 256 + lc4 * 4)
                             : make_float4(0.f, 0.f, 0.f, 0.f);
    }
    wr[0] = *reinterpret_cast<const float4*>(g_W1 + wk0 * 64 + wc0);
    wr[1] = *reinterpret_cast<const float4*>(g_W1 + wk1 * 64 + wc1);

    for (int kk = 0; kk < 8; kk++) {
        // stage current chunk into smem
        *reinterpret_cast<float4*>(&sw[wk0][wc0]) = wr[0];
        *reinterpret_cast<float4*>(&sw[wk1][wc1]) = wr[1];
        #pragma unroll
        for (int q = 0; q < 4; q++) {
            int r = lr + q * 32;
            int rs = r ^ ssw;                          // conflict-free swizzle
            sxT[lc4 * 4 + 0][rs] = xr[q].x;
            sxT[lc4 * 4 + 1][rs] = xr[q].y;
            sxT[lc4 * 4 + 2][rs] = xr[q].z;
            sxT[lc4 * 4 + 3][rs] = xr[q].w;
        }
        __syncthreads();

        // prefetch next chunk while computing
        if (kk < 7) {
            #pragma unroll
            for (int q = 0; q < 4; q++) {
                int n = base + lr + q * 32;
                xr[q] = (n < nNodes)
                    ? *reinterpret_cast<const float4*>(x + (long long)n * 256 + (kk + 1) * 32 + lc4 * 4)
                    : make_float4(0.f, 0.f, 0.f, 0.f);
            }
            wr[0] = *reinterpret_cast<const float4*>(g_W1 + ((kk + 1) * 32 + wk0) * 64 + wc0);
            wr[1] = *reinterpret_cast<const float4*>(g_W1 + ((kk + 1) * 32 + wk1) * 64 + wc1);
        }

        #pragma unroll
        for (int k = 0; k < 32; k++) {
            int rs = (ty * 4) ^ (((k >> 3) & 3) << 2); // read-side swizzle (16B aligned)
            float4 xv = *reinterpret_cast<const float4*>(&sxT[k][rs]);
            ulonglong2 wa = *reinterpret_cast<const ulonglong2*>(&sw[k][tx * 8]);
            ulonglong2 wb = *reinterpret_cast<const ulonglong2*>(&sw[k][tx * 8 + 4]);
            float xs[4] = {xv.x, xv.y, xv.z, xv.w};
            #pragma unroll
            for (int i = 0; i < 4; i++) {
                unsigned long long xp;
                PACK_F32X2(xp, xs[i], xs[i]);
                FMA_F32X2(acc2[i][0], xp, wa.x, acc2[i][0]);
                FMA_F32X2(acc2[i][1], xp, wa.y, acc2[i][1]);
                FMA_F32X2(acc2[i][2], xp, wb.x, acc2[i][2]);
                FMA_F32X2(acc2[i][3], xp, wb.y, acc2[i][3]);
            }
        }
        __syncthreads();
    }

    // epilogue: unpack; init cols scaled by dinv[row]; root cols + bias
    int c = tx * 8;
    #pragma unroll
    for (int i = 0; i < 4; i++) {
        int n = base + ty * 4 + i;
        if (n >= nNodes) break;
        float a[8];
        #pragma unroll
        for (int j = 0; j < 4; j++) UNPACK_F32X2(a[2 * j], a[2 * j + 1], acc2[i][j]);
        if (c < 32) {
            float s = g_dinv[n];
            float4* o = reinterpret_cast<float4*>(g_h1 + (long long)n * 32 + c);
            o[0] = make_float4(a[0] * s, a[1] * s, a[2] * s, a[3] * s);
            o[1] = make_float4(a[4] * s, a[5] * s, a[6] * s, a[7] * s);
        } else {
            int cc = c - 32;
            float4* o = reinterpret_cast<float4*>(g_agg1 + (long long)n * 32 + cc);
            o[0] = make_float4(a[0] + g_b1[cc],     a[1] + g_b1[cc + 1],
                               a[2] + g_b1[cc + 2], a[3] + g_b1[cc + 3]);
            o[1] = make_float4(a[4] + g_b1[cc + 4], a[5] + g_b1[cc + 5],
                               a[6] + g_b1[cc + 6], a[7] + g_b1[cc + 7]);
        }
    }
}

// ---------------- 3-phase exclusive scan of g_deg -> g_off/g_cur ----------
__global__ void k_scanA(int n) {
    __shared__ int sm[256];
    int base = blockIdx.x * 1024;
    int t = threadIdx.x;
    int s = 0;
    #pragma unroll
    for (int j = 0; j < 4; j++) {
        int i = base + t * 4 + j;
        if (i < n) s += g_deg[i];
    }
    sm[t] = s; __syncthreads();
    #pragma unroll
    for (int o = 128; o > 0; o >>= 1) {
        if (t < o) sm[t] += sm[t + o];
        __syncthreads();
    }
    if (t == 0) g_bsum[blockIdx.x] = sm[0];
}
__global__ void k_scanB(int nb) {
    __shared__ int sm[512];
    int t = threadIdx.x;
    int v0 = (t < nb) ? g_bsum[t] : 0;
    sm[t] = v0; __syncthreads();
    #pragma unroll
    for (int o = 1; o < 512; o <<= 1) {
        int v = (t >= o) ? sm[t - o] : 0;
        __syncthreads();
        sm[t] += v;
        __syncthreads();
    }
    if (t < nb) g_boff[t] = sm[t] - v0;    // exclusive
}
__global__ void k_scanC(int n) {
    __shared__ int sm[256];
    int base = blockIdx.x * 1024;
    int t = threadIdx.x;
    int d[4]; int s = 0;
    #pragma unroll
    for (int j = 0; j < 4; j++) {
        int i = base + t * 4 + j;
        d[j] = (i < n) ? g_deg[i] : 0;
        s += d[j];
    }
    sm[t] = s; __syncthreads();
    #pragma unroll
    for (int o = 1; o < 256; o <<= 1) {
        int v = (t >= o) ? sm[t - o] : 0;
        __syncthreads();
        sm[t] += v;
        __syncthreads();
    }
    int excl = sm[t] - s + g_boff[blockIdx.x];
    #pragma unroll
    for (int j = 0; j < 4; j++) {
        int i = base + t * 4 + j;
        if (i < n) { g_off[i] = excl; g_cur[i] = excl; excl += d[j]; }
    }
}

// ---------------- fill CSR (src only, 4B/edge) ----------------
__global__ void k_fill(const int* __restrict__ ei, long long E) {
    long long t = blockIdx.x * 256LL + threadIdx.x;
    if (t >= E) return;
    int is64 = g_is64;
    int s = is64 ? ei[t << 1] : ei[t];
    long long dp = E + t;
    int d = is64 ? ei[dp << 1] : ei[dp];
    int pos = atomicAdd(&g_cur[d], 1);
    g_csrs[pos] = s;
}

// ---------------- gather1: acc = dinv[n]*sum(h1[src]); +root+bias; relu; mean --
__global__ void __launch_bounds__(256) k_gather1(float* __restrict__ hfeat, int nNodes) {
    int t = blockIdx.x * 256 + threadIdx.x;
    int node = t >> 3;
    bool valid = node < nNodes;
    int n = valid ? node : (nNodes - 1);
    int part = t & 7;
    int beg = g_off[n];
    int end = beg + g_deg[n];
    float4 rb = *reinterpret_cast<const float4*>(g_agg1 + ((long long)n << 5) + (part << 2));
    float din = g_dinv[n];
    float4 acc = make_float4(0.f, 0.f, 0.f, 0.f);
    int i = beg;
    for (; i + 4 <= end; i += 4) {
        int s0 = g_csrs[i], s1 = g_csrs[i + 1], s2 = g_csrs[i + 2], s3 = g_csrs[i + 3];
        float4 v0 = *reinterpret_cast<const float4*>(g_h1 + ((long long)s0 << 5) + (part << 2));
        float4 v1 = *reinterpret_cast<const float4*>(g_h1 + ((long long)s1 << 5) + (part << 2));
        float4 v2 = *reinterpret_cast<const float4*>(g_h1 + ((long long)s2 << 5) + (part << 2));
        float4 v3 = *reinterpret_cast<const float4*>(g_h1 + ((long long)s3 << 5) + (part << 2));
        acc.x += v0.x + v1.x + v2.x + v3.x;
        acc.y += v0.y + v1.y + v2.y + v3.y;
        acc.z += v0.z + v1.z + v2.z + v3.z;
        acc.w += v0.w + v1.w + v2.w + v3.w;
    }
    for (; i < end; i++) {
        int s = g_csrs[i];
        float4 v = *reinterpret_cast<const float4*>(g_h1 + ((long long)s << 5) + (part << 2));
        acc.x += v.x; acc.y += v.y; acc.z += v.z; acc.w += v.w;
    }
    acc.x = fmaxf(rb.x + din * acc.x, 0.f);
    acc.y = fmaxf(rb.y + din * acc.y, 0.f);
    acc.z = fmaxf(rb.z + din * acc.z, 0.f);
    acc.w = fmaxf(rb.w + din * acc.w, 0.f);
    float ox = 0.5f * (acc.x + __shfl_xor_sync(0xffffffffu, acc.x, 4));
    float oy = 0.5f * (acc.y + __shfl_xor_sync(0xffffffffu, acc.y, 4));
    float oz = 0.5f * (acc.z + __shfl_xor_sync(0xffffffffu, acc.z, 4));
    float ow = 0.5f * (acc.w + __shfl_xor_sync(0xffffffffu, acc.w, 4));
    if (valid && part < 4) {
        reinterpret_cast<float4*>(hfeat)[((long long)n << 2) + part] =
            make_float4(ox, oy, oz, ow);
        reinterpret_cast<float4*>(g_hfs)[((long long)n << 2) + part] =
            make_float4(ox * din, oy * din, oz * din, ow * din);
    }
}

// ---------------- gather2: aggr[n] = dinv[n] * sum(hfs[src]) ----------------
__global__ void __launch_bounds__(256) k_gather2(int nNodes) {
    int t = blockIdx.x * 256 + threadIdx.x;
    int n = t >> 2;
    if (n >= nNodes) return;
    int part = t & 3;
    int beg = g_off[n];
    int end = beg + g_deg[n];
    float din = g_dinv[n];
    float4 acc = make_float4(0.f, 0.f, 0.f, 0.f);
    int i = beg;
    for (; i + 4 <= end; i += 4) {
        int s0 = g_csrs[i], s1 = g_csrs[i + 1], s2 = g_csrs[i + 2], s3 = g_csrs[i + 3];
        float4 v0 = *reinterpret_cast<const float4*>(g_hfs + ((long long)s0 << 4) + (part << 2));
        float4 v1 = *reinterpret_cast<const float4*>(g_hfs + ((long long)s1 << 4) + (part << 2));
        float4 v2 = *reinterpret_cast<const float4*>(g_hfs + ((long long)s2 << 4) + (part << 2));
        float4 v3 = *reinterpret_cast<const float4*>(g_hfs + ((long long)s3 << 4) + (part << 2));
        acc.x += v0.x + v1.x + v2.x + v3.x;
        acc.y += v0.y + v1.y + v2.y + v3.y;
        acc.z += v0.z + v1.z + v2.z + v3.z;
        acc.w += v0.w + v1.w + v2.w + v3.w;
    }
    for (; i < end; i++) {
        int s = g_csrs[i];
        float4 v = *reinterpret_cast<const float4*>(g_hfs + ((long long)s << 4) + (part << 2));
        acc.x += v.x; acc.y += v.y; acc.z += v.z; acc.w += v.w;
    }
    reinterpret_cast<float4*>(g_aggr)[((long long)n << 2) + part] =
        make_float4(acc.x * din, acc.y * din, acc.z * din, acc.w * din);
}

// ---------------- final: GEMM2 + root + bias, K-mean, log_softmax ----------------
__global__ void __launch_bounds__(256) k_final(const float* __restrict__ hfeat,
                                               float* __restrict__ out, int nNodes) {
    __shared__ float sw[1024];
    __shared__ float sb[32];
    for (int i = threadIdx.x; i < 1024; i += 256) sw[i] = g_W2[i];
    if (threadIdx.x < 32) sb[threadIdx.x] = g_b2[threadIdx.x];
    __syncthreads();
    int n = blockIdx.x * 256 + threadIdx.x;
    if (n >= nNodes) return;

    float hr[16], ag[16];
    const float4* hp = reinterpret_cast<const float4*>(hfeat + (long long)n * 16);
    const float4* ap = reinterpret_cast<const float4*>(g_aggr) + (long long)n * 4;
    #pragma unroll
    for (int j = 0; j < 4; j++) {
        float4 h4 = hp[j], a4 = ap[j];
        hr[4 * j] = h4.x; hr[4 * j + 1] = h4.y; hr[4 * j + 2] = h4.z; hr[4 * j + 3] = h4.w;
        ag[4 * j] = a4.x; ag[4 * j + 1] = a4.y; ag[4 * j + 2] = a4.z; ag[4 * j + 3] = a4.w;
    }

    float l[16];
    #pragma unroll
    for (int o = 0; o < 16; o++) l[o] = 0.f;
    #pragma unroll
    for (int k = 0; k < 2; k++) {
        float acc[16];
        #pragma unroll
        for (int o = 0; o < 16; o++) acc[o] = sb[k * 16 + o];
        #pragma unroll
        for (int f = 0; f < 16; f++) {
            float av = ag[f], hv = hr[f];
            const float* wi = sw + f * 64 + k * 16;       // init
            const float* wr = wi + 32;                    // root
            #pragma unroll
            for (int o = 0; o < 16; o++)
                acc[o] += av * wi[o] + hv * wr[o];
        }
        #pragma unroll
        for (int o = 0; o < 16; o++) l[o] += 0.5f * acc[o];
    }

    float m = l[0];
    #pragma unroll
    for (int i = 1; i < 16; i++) m = fmaxf(m, l[i]);
    float s = 0.f;
    #pragma unroll
    for (int i = 0; i < 16; i++) s += expf(l[i] - m);
    float lg = m + logf(s);
    float4* o4 = reinterpret_cast<float4*>(out + (long long)n * 16);
    #pragma unroll
    for (int j = 0; j < 4; j++)
        o4[j] = make_float4(l[4 * j] - lg, l[4 * j + 1] - lg,
                            l[4 * j + 2] - lg, l[4 * j + 3] - lg);
}

// ---------------- launch ----------------
extern "C" void kernel_launch(void* const* d_in, const int* in_sizes, int n_in,
                              void* d_out, int out_size) {
    const float* x   = (const float*)d_in[0];
    const int*   ei  = (const int*)d_in[1];
    const float* iw1 = (const float*)d_in[2];
    const float* rw1 = (const float*)d_in[3];
    const float* b1  = (const float*)d_in[4];
    const float* iw2 = (const float*)d_in[5];
    const float* rw2 = (const float*)d_in[6];
    const float* b2  = (const float*)d_in[7];
    float* out = (float*)d_out;

    int N = in_sizes[0] / 256;
    long long E = in_sizes[1] / 2;
    float* hfeat = out + (long long)N * 16;   // agg_feature region of d_out

    int nbN  = (N + 255) / 256;
    int nbSc = (N + 1023) / 1024;
    int nbE  = (int)((E + 255) / 256);
    int nbG1 = (N * 8 + 255) / 256;
    int nbG2 = (N * 4 + 255) / 256;
    int nbP  = nbN > ((16384 + 1024 + 64 + 255) / 256) ? nbN : ((16384 + 1024 + 64 + 255) / 256);

    k_prepzero<<<nbP, 256>>>(ei, N, iw1, rw1, b1, iw2, rw2, b2);
    k_deg    <<<nbE, 256>>>(ei, E);
    k_dinv   <<<nbN, 256>>>(N);
    k_gemm1  <<<(N + 127) / 128, 256>>>(x, N);
    k_scanA  <<<nbSc, 256>>>(N);
    k_scanB  <<<1, 512>>>(nbSc);
    k_scanC  <<<nbSc, 256>>>(N);
    k_fill   <<<nbE, 256>>>(ei, E);
    k_gather1<<<nbG1, 256>>>(hfeat, N);
    k_gather2<<<nbG2, 256>>>(N);
    k_final  <<<nbN, 256>>>(hfeat, out, N);
}